// round 14
// baseline (speedup 1.0000x reference)
#include <cuda_runtime.h>
#include <cuda_fp16.h>
#include <math.h>
#include <stdint.h>

// ---------------- problem constants ----------------
#define IH 384
#define IW 384
#define NPIX (IH*IW)
#define NIMG 4
#define NT 577
#define DM 768
#define NL 12
#define NHD 12
#define BT (NIMG*NT)    // 2308
#define NPATCH 576
#define BIGF 1e4f
#define SPF 640

// static scales
#define WS  4096.f
#define AS  256.f
#define PS  32.f
#define SS  256.f

// ---------------- scratch ----------------
__device__ float d_g2fg[NIMG*NPIX];
__device__ float d_g2bg[NIMG*NPIX];
__device__ float d_tok [NIMG*NPATCH*DM];
__device__ float d_x   [BT*DM];
__device__ float d_h   [BT*DM];
__device__ __align__(128) float d_S[(size_t)NIMG*NHD*NT*SPF];
__device__ float2 d_rs [NIMG*NHD*NT];
__device__ float d_part[(size_t)4*BT*DM];

__device__ __align__(128) __half d_h0[BT*DM],    d_h1[BT*DM];
__device__ __align__(128) __half d_a0[BT*DM],    d_a1[BT*DM];
__device__ __align__(128) __half d_m0[BT*3072],  d_m1[BT*3072];
__device__ __align__(128) __half d_p0[NIMG*NPATCH*256], d_p1[NIMG*NPATCH*256];
__device__ __align__(128) __half d_q0[BT*3*DM],  d_q1[BT*3*DM];

__device__ __align__(128) __half d_ws0[DM*256],       d_ws1[DM*256];
__device__ __align__(128) __half d_qT0[NL*2304*DM],   d_qT1[NL*2304*DM];
__device__ __align__(128) __half d_pT0[NL*DM*DM],     d_pT1[NL*DM*DM];
__device__ __align__(128) __half d_f1T0[NL*3072*DM],  d_f1T1[NL*3072*DM];
__device__ __align__(128) __half d_f2T0[NL*DM*3072],  d_f2T1[NL*DM*3072];

// ---------------- helpers ----------------
__device__ __forceinline__ void split2h(float x, float s, __half& h0, __half& h1) {
    float xs = x * s;
    h0 = __float2half_rn(xs);
    h1 = __float2half_rn(xs - __half2float(h0));
}
__device__ __forceinline__ uint32_t s2u(const void* p) {
    uint32_t a;
    asm("{ .reg .u64 t; cvta.to.shared.u64 t, %1; cvt.u32.u64 %0, t; }" : "=r"(a) : "l"(p));
    return a;
}
#define CP16(s,g)  asm volatile("cp.async.cg.shared.global [%0], [%1], 16;" :: "r"(s), "l"(g))
#define CPCOMMIT() asm volatile("cp.async.commit_group;")
#define CPWAIT0()  asm volatile("cp.async.wait_group 0;")

__device__ __forceinline__ void ldsm4(unsigned &r0, unsigned &r1, unsigned &r2,
                                      unsigned &r3, uint32_t addr) {
    asm volatile("ldmatrix.sync.aligned.m8n8.x4.shared.b16 {%0,%1,%2,%3}, [%4];"
        : "=r"(r0), "=r"(r1), "=r"(r2), "=r"(r3) : "r"(addr));
}
__device__ __forceinline__ void ldsm4t(unsigned &r0, unsigned &r1, unsigned &r2,
                                       unsigned &r3, uint32_t addr) {
    asm volatile("ldmatrix.sync.aligned.m8n8.x4.trans.shared.b16 {%0,%1,%2,%3}, [%4];"
        : "=r"(r0), "=r"(r1), "=r"(r2), "=r"(r3) : "r"(addr));
}
#define MMA_F16(c, a, b0v, b1v) \
    asm volatile("mma.sync.aligned.m16n8k16.row.col.f32.f16.f16.f32 " \
                 "{%0,%1,%2,%3},{%4,%5,%6,%7},{%8,%9},{%0,%1,%2,%3};" \
                 : "+f"((c)[0]), "+f"((c)[1]), "+f"((c)[2]), "+f"((c)[3]) \
                 : "r"((a)[0]), "r"((a)[1]), "r"((a)[2]), "r"((a)[3]), \
                   "r"(b0v), "r"(b1v))

// ---------------- EDT row pass (mask fused) ----------------
__global__ void k_edt_row(const float* __restrict__ logits, const int* __restrict__ tr) {
    int idx = blockIdx.x*blockDim.x + threadIdx.x;
    if (idx >= NIMG*IH) return;
    int img = idx / IH, i = idx % IH;
    float* gf = d_g2fg + (size_t)img*NPIX + (size_t)i*IW;
    float* gb = d_g2bg + (size_t)img*NPIX + (size_t)i*IW;
    const float* l0p = logits + ((size_t)img*2)*NPIX + (size_t)i*IW;
    const float* l1p = l0p + NPIX;
    const int*   trp = tr + (size_t)(img-2)*NPIX + (size_t)i*IW;
    bool islog = (img < 2);

    float lf = -BIGF, lb = -BIGF;
    for (int j = 0; j < IW; j++) {
        bool mz = islog ? !(l1p[j] > l0p[j]) : (trp[j] == 0);
        float jj = (float)j;
        if (mz) lf = jj; else lb = jj;
        gf[j] = jj - lf;
        gb[j] = jj - lb;
    }
    float rf = BIGF, rb = BIGF;
    for (int j = IW-1; j >= 0; j--) {
        bool mz = islog ? !(l1p[j] > l0p[j]) : (trp[j] == 0);
        float jj = (float)j;
        if (mz) rf = jj; else rb = jj;
        float g1 = fminf(fminf(gf[j], rf - jj), BIGF);
        float g2 = fminf(fminf(gb[j], rb - jj), BIGF);
        gf[j] = g1*g1;
        gb[j] = g2*g2;
    }
}

// ---------------- EDT column pass + SDM + patch-split write ----------------
__global__ void k_edt_col() {
    int idx = blockIdx.x*blockDim.x + threadIdx.x;
    if (idx >= NIMG*NPIX) return;
    int img = idx / NPIX, r = idx % NPIX;
    int i = r / IW, j = r % IW;
    const float* gf = d_g2fg + (size_t)img*NPIX;
    const float* gb = d_g2bg + (size_t)img*NPIX;
    float mf = 3.4e38f, mb = 3.4e38f;
    float fi = (float)i;
    for (int ii = 0; ii < IH; ii++) {
        float off = fi - (float)ii; off *= off;
        mf = fminf(mf, gf[(size_t)ii*IW + j] + off);
        mb = fminf(mb, gb[(size_t)ii*IW + j] + off);
    }
    float v = sqrtf(mb) - sqrtf(mf);
    int t = (i >> 4)*24 + (j >> 4);
    int k = ((i & 15) << 4) + (j & 15);
    size_t o = (size_t)img*NPATCH*256 + (size_t)t*256 + k;
    split2h(v, PS, d_p0[o], d_p1[o]);
}

// ---------------- weight prep ----------------
__global__ void k_wsumT(const float* __restrict__ pw) {
    int idx = blockIdx.x*blockDim.x + threadIdx.x;
    if (idx >= DM*256) return;
    int o = idx / 256, k = idx % 256;
    float v = pw[(size_t)k*DM + o] + pw[(size_t)(256+k)*DM + o] + pw[(size_t)(512+k)*DM + o];
    split2h(v, WS, d_ws0[idx], d_ws1[idx]);
}

__global__ void k_tsplit(const float* __restrict__ W, __half* __restrict__ T0,
                         __half* __restrict__ T1, int K, int N) {
    __shared__ float t[32][33];
    size_t off = (size_t)blockIdx.z * K * N;
    const float* w = W + off;
    int bx = blockIdx.x*32, by = blockIdx.y*32;
    int tx = threadIdx.x, ty = threadIdx.y;
    #pragma unroll
    for (int r = 0; r < 4; r++)
        t[ty + r*8][tx] = w[(size_t)(by + ty + r*8)*N + bx + tx];
    __syncthreads();
    #pragma unroll
    for (int r = 0; r < 4; r++) {
        int n = bx + ty + r*8, k = by + tx;
        float v = t[tx][ty + r*8];
        size_t o = off + (size_t)n*K + k;
        split2h(v, WS, T0[o], T1[o]);
    }
}

__global__ void k_assemble(const float* __restrict__ cls, const float* __restrict__ pos) {
    int idx = blockIdx.x*blockDim.x + threadIdx.x;
    if (idx >= BT*DM) return;
    int img = idx / (NT*DM);
    int rem = idx % (NT*DM);
    int t = rem / DM, c = rem % DM;
    float v = (t == 0) ? cls[c] : d_tok[((size_t)img*NPATCH + (t-1))*DM + c];
    d_x[idx] = v + pos[(size_t)t*DM + c];
}

// ---------------- layernorm (split planes only) ----------------
__global__ void k_ln(const float* __restrict__ in,
                     const float* __restrict__ g, const float* __restrict__ b) {
    int row = blockIdx.x;
    int tid = threadIdx.x;
    const float* xr = in + (size_t)row*DM;
    __shared__ float red[256];
    float v[3];
    #pragma unroll
    for (int i = 0; i < 3; i++) v[i] = xr[tid + i*256];
    float s = v[0] + v[1] + v[2];
    red[tid] = s; __syncthreads();
    for (int o = 128; o > 0; o >>= 1) { if (tid < o) red[tid] += red[tid+o]; __syncthreads(); }
    float mu = red[0] * (1.f/768.f);
    __syncthreads();
    float var = 0.f;
    #pragma unroll
    for (int i = 0; i < 3; i++) { float dd = v[i]-mu; var += dd*dd; }
    red[tid] = var; __syncthreads();
    for (int o = 128; o > 0; o >>= 1) { if (tid < o) red[tid] += red[tid+o]; __syncthreads(); }
    float rstd = rsqrtf(red[0] * (1.f/768.f) + 1e-6f);
    #pragma unroll
    for (int i = 0; i < 3; i++) {
        int c = tid + i*256;
        float val = (v[i]-mu)*rstd*g[c] + b[c];
        size_t o = (size_t)row*DM + c;
        split2h(val, AS, d_h0[o], d_h1[o]);
    }
}

// ---------------- fused split-K reduce + residual + LN + split write --------
__global__ void k_redln(const float* __restrict__ P, int ns, float inv,
                        const float* __restrict__ bias, float* __restrict__ x,
                        const float* __restrict__ g, const float* __restrict__ b) {
    int row = blockIdx.x;
    int tid = threadIdx.x;
    __shared__ float red[256];
    const size_t MN = (size_t)BT*DM;
    float v[3];
    #pragma unroll
    for (int i = 0; i < 3; i++) {
        int c = tid + i*256;
        size_t o = (size_t)row*DM + c;
        float s = P[o];
        for (int z = 1; z < ns; z++) s += P[(size_t)z*MN + o];
        v[i] = s*inv + bias[c] + x[o];
        x[o] = v[i];
    }
    float s = v[0] + v[1] + v[2];
    red[tid] = s; __syncthreads();
    for (int o = 128; o > 0; o >>= 1) { if (tid < o) red[tid] += red[tid+o]; __syncthreads(); }
    float mu = red[0] * (1.f/768.f);
    __syncthreads();
    float var = 0.f;
    #pragma unroll
    for (int i = 0; i < 3; i++) { float dd = v[i]-mu; var += dd*dd; }
    red[tid] = var; __syncthreads();
    for (int o = 128; o > 0; o >>= 1) { if (tid < o) red[tid] += red[tid+o]; __syncthreads(); }
    float rstd = rsqrtf(red[0] * (1.f/768.f) + 1e-6f);
    #pragma unroll
    for (int i = 0; i < 3; i++) {
        int c = tid + i*256;
        float val = (v[i]-mu)*rstd*g[c] + b[c];
        size_t o = (size_t)row*DM + c;
        split2h(val, AS, d_h0[o], d_h1[o]);
    }
}

// ---------------- final LN on the 4 cls rows only ----------------
__global__ void k_lncls(const float* __restrict__ in, float* __restrict__ out,
                        const float* __restrict__ g, const float* __restrict__ b) {
    int row = blockIdx.x * NT;
    int tid = threadIdx.x;
    const float* xr = in + (size_t)row*DM;
    __shared__ float red[256];
    float v[3];
    #pragma unroll
    for (int i = 0; i < 3; i++) v[i] = xr[tid + i*256];
    float s = v[0] + v[1] + v[2];
    red[tid] = s; __syncthreads();
    for (int o = 128; o > 0; o >>= 1) { if (tid < o) red[tid] += red[tid+o]; __syncthreads(); }
    float mu = red[0] * (1.f/768.f);
    __syncthreads();
    float var = 0.f;
    #pragma unroll
    for (int i = 0; i < 3; i++) { float dd = v[i]-mu; var += dd*dd; }
    red[tid] = var; __syncthreads();
    for (int o = 128; o > 0; o >>= 1) { if (tid < o) red[tid] += red[tid+o]; __syncthreads(); }
    float rstd = rsqrtf(red[0] * (1.f/768.f) + 1e-6f);
    #pragma unroll
    for (int i = 0; i < 3; i++) {
        int c = tid + i*256;
        out[(size_t)row*DM + c] = (v[i]-mu)*rstd*g[c] + b[c];
    }
}

// ---------------- shared epilogue ----------------
__device__ __forceinline__ void gemm_epilogue(
        float v0, float v1, int gr, int gc, int N, int epi,
        const float* res, float* C, __half* C0, __half* C1) {
    if (epi == 1 || epi == 3) {
        if (epi == 1) {
            v0 = 0.5f*v0*(1.f + erff(v0*0.70710678118654752f));
            v1 = 0.5f*v1*(1.f + erff(v1*0.70710678118654752f));
        }
        size_t o = (size_t)gr*N + gc;
        __half h00, h01, h10, h11;
        split2h(v0, AS, h00, h01);
        split2h(v1, AS, h10, h11);
        __half2 p0; p0.x = h00; p0.y = h10;
        __half2 p1; p1.x = h01; p1.y = h11;
        *(__half2*)&C0[o] = p0;
        *(__half2*)&C1[o] = p1;
    } else {
        if (epi == 2) {
            float2 r2 = *(const float2*)&res[(size_t)gr*N + gc];
            v0 += r2.x; v1 += r2.y;
        }
        *(float2*)&C[(size_t)gr*N + gc] = make_float2(v0, v1);
    }
}

// ================= unified GEMM: 512 threads, 128x128 tile, BK=64 ===========
// epi: 0 bias->C; 1 gelu->C0/C1; 2 bias+res->C; 3 bias->C0/C1;
//      4 raw partial -> C (+ blockIdx.z*M*N).  K = slice len, LDK = row stride.
#define G64_ROW 144u
#define G64_PL  (128u*G64_ROW)          // 18432 per plane
#define G64_BUF (4u*G64_PL)             // 73728: A0 A1 B0 B1
#define SMEM_G64 (2u*G64_BUF)           // 147456

__global__ __launch_bounds__(512, 1) void k_g64(
        const __half* __restrict__ A0, const __half* __restrict__ A1,
        const __half* __restrict__ B0, const __half* __restrict__ B1,
        const float* __restrict__ bias, const float* __restrict__ res,
        float* __restrict__ C, __half* __restrict__ C0, __half* __restrict__ C1,
        int M, int N, int K, int LDK, float inv, int epi) {
    extern __shared__ char smem[];
    uint32_t sb = s2u(smem);
    int tid = threadIdx.x, lane = tid & 31, warp = tid >> 5;
    int wm = (warp & 3)*32, wn = (warp >> 2)*32;
    int bm = blockIdx.y*128, bn = blockIdx.x*128;
    size_t koff = (size_t)blockIdx.z * K;
    int g = lane >> 2, q = lane & 3;

    float acc[2][4][4];
    #pragma unroll
    for (int i=0;i<2;i++)
        #pragma unroll
        for (int j=0;j<4;j++)
            #pragma unroll
            for (int r=0;r<4;r++) acc[i][j][r]=0.f;

    int lrow = tid >> 2;    // 0..127
    int lc   = tid & 3;     // chunks lc and lc+4

    auto load_chunk = [&](int kt, int buf) {
        int k0 = kt * 64;
        uint32_t base = sb + (uint32_t)buf * G64_BUF;
        const __half* Ap[2] = {A0, A1};
        const __half* Bp[2] = {B0, B1};
        int gra = bm + lrow; if (gra >= M) gra = M - 1;
        #pragma unroll
        for (int p = 0; p < 2; p++) {
            size_t ga = (size_t)gra*LDK + koff + k0;
            size_t gb = (size_t)(bn + lrow)*LDK + koff + k0;
            #pragma unroll
            for (int h = 0; h < 2; h++) {
                int cc = lc + h*4;
                CP16(base + p*G64_PL + (uint32_t)(lrow*G64_ROW + cc*16),
                     Ap[p] + ga + cc*8);
                CP16(base + 2*G64_PL + p*G64_PL + (uint32_t)(lrow*G64_ROW + cc*16),
                     Bp[p] + gb + cc*8);
            }
        }
    };

    int KT = K >> 6;
    load_chunk(0, 0);
    CPCOMMIT();
    for (int kt = 0; kt < KT; kt++) {
        CPWAIT0();
        __syncthreads();
        if (kt + 1 < KT) { load_chunk(kt + 1, (kt + 1) & 1); CPCOMMIT(); }
        uint32_t base = sb + (uint32_t)(kt & 1) * G64_BUF;
        uint32_t aBase = base + (uint32_t)((wm + (lane & 15))*G64_ROW + (lane >> 4)*16);
        int bn8 = (lane & 7) + ((lane >> 4) << 3);
        uint32_t bBase = base + 2*G64_PL +
                         (uint32_t)((wn + bn8)*G64_ROW + ((lane >> 3) & 1)*16);
        #pragma unroll
        for (int ks = 0; ks < 4; ks++) {
            unsigned a0f[2][4], a1f[2][4];
            #pragma unroll
            for (int mi = 0; mi < 2; mi++) {
                ldsm4(a0f[mi][0],a0f[mi][1],a0f[mi][2],a0f[mi][3],
                      aBase + mi*16*G64_ROW + ks*32u);
                ldsm4(a1f[mi][0],a1f[mi][1],a1f[mi][2],a1f[mi][3],
                      aBase + G64_PL + mi*16*G64_ROW + ks*32u);
            }
            #pragma unroll
            for (int nq = 0; nq < 2; nq++) {
                unsigned b0f[4], b1f[4];
                ldsm4(b0f[0],b0f[1],b0f[2],b0f[3],
                      bBase + nq*16*G64_ROW + ks*32u);
                ldsm4(b1f[0],b1f[1],b1f[2],b1f[3],
                      bBase + G64_PL + nq*16*G64_ROW + ks*32u);
                #pragma unroll
                for (int mi = 0; mi < 2; mi++)
                    #pragma unroll
                    for (int h = 0; h < 2; h++) {
                        MMA_F16(acc[mi][nq*2+h], a0f[mi], b0f[h*2], b0f[h*2+1]);
                        MMA_F16(acc[mi][nq*2+h], a0f[mi], b1f[h*2], b1f[h*2+1]);
                        MMA_F16(acc[mi][nq*2+h], a1f[mi], b0f[h*2], b0f[h*2+1]);
                    }
            }
        }
        __syncthreads();
    }

    size_t pofs = (size_t)blockIdx.z * M * N;
    #pragma unroll
    for (int mi = 0; mi < 2; mi++)
        #pragma unroll
        for (int rr = 0; rr < 2; rr++) {
            int gr = bm + wm + mi*16 + g + rr*8;
            if (gr >= M) continue;
            #pragma unroll
            for (int nj = 0; nj < 4; nj++) {
                int gc = bn + wn + nj*8 + 2*q;
                if (epi == 4) {
                    *(float2*)&C[pofs + (size_t)gr*N + gc] =
                        make_float2(acc[mi][nj][rr*2+0], acc[mi][nj][rr*2+1]);
                } else {
                    gemm_epilogue(acc[mi][nj][rr*2+0]*inv + bias[gc],
                                  acc[mi][nj][rr*2+1]*inv + bias[gc+1],
                                  gr, gc, N, epi, res, C, C0, C1);
                }
            }
        }
}

// ---------------- split-K reduce (plain; last layer fc2) ----------------
__global__ void k_red(const float* __restrict__ P, int ns, float inv,
                      const float* __restrict__ bias, const float* __restrict__ res,
                      float* __restrict__ C, int N, int total4) {
    int t = blockIdx.x*blockDim.x + threadIdx.x;
    if (t >= total4) return;
    size_t i = (size_t)t * 4;
    size_t MN = (size_t)total4 * 4;
    float4 s = *(const float4*)&P[i];
    for (int z = 1; z < ns; z++) {
        float4 p = *(const float4*)&P[(size_t)z*MN + i];
        s.x += p.x; s.y += p.y; s.z += p.z; s.w += p.w;
    }
    int c = (int)(i % N);
    float4 b = *(const float4*)&bias[c];
    float4 r = *(const float4*)&res[i];
    s.x = s.x*inv + b.x + r.x;
    s.y = s.y*inv + b.y + r.y;
    s.z = s.z*inv + b.z + r.z;
    s.w = s.w*inv + b.w + r.w;
    *(float4*)&C[i] = s;
}

// ================= attention scores (fp32 out, padded stride SPF) ===========
#define SROW 144u
#define SPL  (128u*SROW)
#define SMEM_SC (4u*SPL)

__global__ __launch_bounds__(256, 2) void k_scores_h() {
    extern __shared__ char smem[];
    uint32_t sb = s2u(smem);
    int bh = blockIdx.z, b = bh / NHD, h = bh % NHD;
    int m0 = blockIdx.y*128, n0 = blockIdx.x*128;
    int tid = threadIdx.x, lane = tid & 31, warp = tid >> 5;
    int wm = (warp & 3)*32, wn = (warp >> 2)*64;
    int g = lane >> 2, q = lane & 3;

    #pragma unroll
    for (int l = 0; l < 4; l++) {
        int id = tid + l*256;
        int row = id >> 3, c = id & 7;
        int gm = m0 + row; if (gm >= NT) gm = NT - 1;
        int gn = n0 + row; if (gn >= NT) gn = NT - 1;
        size_t qo = (size_t)(b*NT + gm)*2304 + h*64 + c*8;
        size_t ko = (size_t)(b*NT + gn)*2304 + 768 + h*64 + c*8;
        uint32_t so = (uint32_t)(row*SROW + c*16);
        CP16(sb + so,          d_q0 + qo);
        CP16(sb + SPL + so,    d_q1 + qo);
        CP16(sb + 2*SPL + so,  d_q0 + ko);
        CP16(sb + 3*SPL + so,  d_q1 + ko);
    }
    CPCOMMIT(); CPWAIT0();
    __syncthreads();

    float acc[2][8][4];
    #pragma unroll
    for (int i=0;i<2;i++)
        #pragma unroll
        for (int j=0;j<8;j++)
            #pragma unroll
            for (int r=0;r<4;r++) acc[i][j][r]=0.f;

    uint32_t aBase = sb + (uint32_t)((wm + (lane & 15))*SROW + (lane >> 4)*16);
    int bn8 = (lane & 7) + ((lane >> 4) << 3);
    uint32_t bBase = sb + 2*SPL + (uint32_t)((wn + bn8)*SROW + ((lane >> 3) & 1)*16);

    #pragma unroll
    for (int ks = 0; ks < 4; ks++) {
        unsigned a0f[2][4], a1f[2][4];
        #pragma unroll
        for (int mi = 0; mi < 2; mi++) {
            ldsm4(a0f[mi][0],a0f[mi][1],a0f[mi][2],a0f[mi][3],
                  aBase + mi*16*SROW + ks*32u);
            ldsm4(a1f[mi][0],a1f[mi][1],a1f[mi][2],a1f[mi][3],
                  aBase + SPL + mi*16*SROW + ks*32u);
        }
        #pragma unroll
        for (int nq = 0; nq < 4; nq++) {
            unsigned b0f[4], b1f[4];
            ldsm4(b0f[0],b0f[1],b0f[2],b0f[3], bBase + nq*16*SROW + ks*32u);
            ldsm4(b1f[0],b1f[1],b1f[2],b1f[3], bBase + SPL + nq*16*SROW + ks*32u);
            #pragma unroll
            for (int mi = 0; mi < 2; mi++)
                #pragma unroll
                for (int hh = 0; hh < 2; hh++) {
                    MMA_F16(acc[mi][nq*2+hh], a0f[mi], b0f[hh*2], b0f[hh*2+1]);
                    MMA_F16(acc[mi][nq*2+hh], a0f[mi], b1f[hh*2], b1f[hh*2+1]);
                    MMA_F16(acc[mi][nq*2+hh], a1f[mi], b0f[hh*2], b0f[hh*2+1]);
                }
        }
    }

    const float SCL = 0.125f/(AS*AS);
    float* sbase = d_S + (size_t)bh*NT*SPF;
    #pragma unroll
    for (int mi = 0; mi < 2; mi++)
        #pragma unroll
        for (int rr = 0; rr < 2; rr++) {
            int gm = m0 + wm + mi*16 + g + rr*8;
            if (gm >= NT) continue;
            #pragma unroll
            for (int nj = 0; nj < 8; nj++) {
                int gc = n0 + wn + nj*8 + 2*q;
                if (gc < NT)   sbase[(size_t)gm*SPF + gc]   = acc[mi][nj][rr*2+0]*SCL;
                if (gc+1 < NT) sbase[(size_t)gm*SPF + gc+1] = acc[mi][nj][rr*2+1]*SCL;
            }
        }
}

// ---------------- row stats ----------------
__global__ void k_rowstat() {
    size_t row = blockIdx.x;
    const float* s = d_S + row*SPF;
    int tid = threadIdx.x;
    __shared__ float red[128];
    float v[5];
    float mx = -3.4e38f;
    #pragma unroll
    for (int i = 0; i < 5; i++) {
        int c = tid + i*128;
        v[i] = (c < NT) ? s[c] : -3.4e38f;
        mx = fmaxf(mx, v[i]);
    }
    red[tid] = mx; __syncthreads();
    for (int o = 64; o > 0; o >>= 1) { if (tid < o) red[tid] = fmaxf(red[tid], red[tid+o]); __syncthreads(); }
    mx = red[0]; __syncthreads();
    float sum = 0.f;
    #pragma unroll
    for (int i = 0; i < 5; i++) sum += __expf(v[i] - mx);
    red[tid] = sum; __syncthreads();
    for (int o = 64; o > 0; o >>= 1) { if (tid < o) red[tid] += red[tid+o]; __syncthreads(); }
    if (tid == 0) d_rs[row] = make_float2(mx, SS / red[0]);
}

// ================= AV: fused exp/normalize + split + MMA ====================
#define AV_RS   0u
#define AV_P0   1024u
#define AV_P1   11264u
#define AV_BUF0 21504u
#define AV_FB   18432u
#define AV_VPL  4608u
#define AV_BUFSZ (AV_FB + 2u*AV_VPL)
#define SMEM_AV (AV_BUF0 + 2u*AV_BUFSZ)

__global__ __launch_bounds__(256, 2) void k_av_h() {
    extern __shared__ char smem[];
    uint32_t sb = s2u(smem);
    int bh = blockIdx.y, b = bh / NHD, h = bh % NHD;
    int m0 = blockIdx.x*128;
    int tid = threadIdx.x, lane = tid & 31, warp = tid >> 5;
    int wm = (warp & 3)*32, wn = (warp >> 2)*32;
    int g = lane >> 2, q = lane & 3;

    float acc[2][4][4];
    #pragma unroll
    for (int i=0;i<2;i++)
        #pragma unroll
        for (int j=0;j<4;j++)
            #pragma unroll
            for (int r=0;r<4;r++) acc[i][j][r]=0.f;

    const float* Sf = d_S + (size_t)bh*NT*SPF;

    if (tid < 128) {
        int gm = m0 + tid; if (gm >= NT) gm = NT - 1;
        *(float2*)(smem + AV_RS + tid*8) = d_rs[(size_t)bh*NT + gm];
    }

    auto load_chunk = [&](int kt, int buf) {
        int k0 = kt * 32;
        uint32_t base = sb + AV_BUF0 + (uint32_t)buf * AV_BUFSZ;
        #pragma unroll
        for (int l = 0; l < 4; l++) {
            int id = tid + l*256;
            int row = id >> 3, c = id & 7;
            int gm = m0 + row; if (gm >= NT) gm = NT - 1;
            CP16(base + (uint32_t)(row*144 + c*16),
                 Sf + (size_t)gm*SPF + k0 + c*4);
        }
        {
            int row = tid >> 3, c = tid & 7;
            int gk = k0 + row; if (gk >= NT) gk = NT - 1;
            size_t vo = (size_t)(b*NT + gk)*2304 + 1536 + h*64 + c*8;
            uint32_t d = (uint32_t)(row*144 + c*16);
            CP16(base + AV_FB + d,           d_q0 + vo);
            CP16(base + AV_FB + AV_VPL + d,  d_q1 + vo);
        }
    };

    const int KT = (NT + 31) / 32;   // 19
    load_chunk(0, 0);
    CPCOMMIT();
    for (int kt = 0; kt < KT; kt++) {
        int buf = kt & 1;
        int k0 = kt * 32;
        CPWAIT0();
        __syncthreads();
        if (kt + 1 < KT) { load_chunk(kt + 1, (kt + 1) & 1); CPCOMMIT(); }
        {
            int row = tid >> 1, colh = (tid & 1)*16;
            float2 ri = *(const float2*)(smem + AV_RS + row*8);
            const float* F = (const float*)(smem + AV_BUF0 + buf*AV_BUFSZ) + row*36 + colh;
            char* P0w = smem + AV_P0 + row*80 + colh*2;
            char* P1w = smem + AV_P1 + row*80 + colh*2;
            #pragma unroll
            for (int j = 0; j < 16; j += 2) {
                int k = k0 + colh + j;
                float f0 = F[j], f1 = F[j+1];
                float p0 = (k     < NT) ? __expf(f0 - ri.x)*ri.y : 0.f;
                float p1 = (k + 1 < NT) ? __expf(f1 - ri.x)*ri.y : 0.f;
                __half a0h = __float2half_rn(p0);
                __half b0h = __float2half_rn(p1);
                __half a1h = __float2half_rn(p0 - __half2float(a0h));
                __half b1h = __float2half_rn(p1 - __half2float(b0h));
                __half2 w0; w0.x = a0h; w0.y = b0h;
                __half2 w1; w1.x = a1h; w1.y = b1h;
                *(__half2*)(P0w + j*2) = w0;
                *(__half2*)(P1w + j*2) = w1;
            }
        }
        __syncthreads();
        uint32_t aBase = sb + AV_P0 + (uint32_t)((wm + (lane & 15))*80 + (lane >> 4)*16);
        uint32_t vb0 = sb + AV_BUF0 + (uint32_t)buf*AV_BUFSZ + AV_FB;
        uint32_t bBase = vb0 + (uint32_t)((lane & 15)*144 + wn*2 + (lane >> 4)*16);
        #pragma unroll
        for (int ks = 0; ks < 2; ks++) {
            unsigned a0f[2][4], a1f[2][4];
            #pragma unroll
            for (int mi = 0; mi < 2; mi++) {
                ldsm4(a0f[mi][0],a0f[mi][1],a0f[mi][2],a0f[mi][3],
                      aBase + mi*16*80u + ks*32u);
                ldsm4(a1f[mi][0],a1f[mi][1],a1f[mi][2],a1f[mi][3],
                      aBase + (AV_P1 - AV_P0) + mi*16*80u + ks*32u);
            }
            #pragma unroll
            for (int nq = 0; nq < 2; nq++) {
                unsigned b0f[4], b1f[4];
                uint32_t ba = bBase + ks*16*144u + nq*32u;
                ldsm4t(b0f[0],b0f[1],b0f[2],b0f[3], ba);
                ldsm4t(b1f[0],b1f[1],b1f[2],b1f[3], ba + AV_VPL);
                #pragma unroll
                for (int mi = 0; mi < 2; mi++)
                    #pragma unroll
                    for (int hh = 0; hh < 2; hh++) {
                        MMA_F16(acc[mi][nq*2+hh], a0f[mi], b0f[hh*2], b0f[hh*2+1]);
                        MMA_F16(acc[mi][nq*2+hh], a0f[mi], b1f[hh*2], b1f[hh*2+1]);
                        MMA_F16(acc[mi][nq*2+hh], a1f[mi], b0f[hh*2], b0f[hh*2+1]);
                    }
            }
        }
    }

    const float INV_AV = 1.f/(SS*AS);
    #pragma unroll
    for (int mi = 0; mi < 2; mi++)
        #pragma unroll
        for (int rr = 0; rr < 2; rr++) {
            int gm = m0 + wm + mi*16 + g + rr*8;
            if (gm >= NT) continue;
            #pragma unroll
            for (int nj = 0; nj < 4; nj++) {
                int gc = wn + nj*8 + 2*q;
                size_t o = (size_t)(b*NT + gm)*DM + h*64 + gc;
                float v0 = acc[mi][nj][rr*2+0]*INV_AV;
                float v1 = acc[mi][nj][rr*2+1]*INV_AV;
                __half h00, h01, h10, h11;
                split2h(v0, AS, h00, h01);
                split2h(v1, AS, h10, h11);
                __half2 p0; p0.x = h00; p0.y = h10;
                __half2 p1; p1.x = h01; p1.y = h11;
                *(__half2*)&d_a0[o] = p0;
                *(__half2*)&d_a1[o] = p1;
            }
        }
}

// ---------------- final cosine loss ----------------
__global__ void k_loss(float* out) {
    __shared__ float sd[256], sa[256], sb2[256];
    int tid = threadIdx.x;
    float coss[2];
    for (int b = 0; b < 2; b++) {
        const float* fp = d_h + (size_t)b*NT*DM;
        const float* ft = d_h + (size_t)(2+b)*NT*DM;
        float dt = 0.f, na = 0.f, nb = 0.f;
        for (int c = tid; c < DM; c += 256) {
            float a = fp[c], bb = ft[c];
            dt += a*bb; na += a*a; nb += bb*bb;
        }
        sd[tid] = dt; sa[tid] = na; sb2[tid] = nb; __syncthreads();
        for (int o = 128; o > 0; o >>= 1) {
            if (tid < o) { sd[tid]+=sd[tid+o]; sa[tid]+=sa[tid+o]; sb2[tid]+=sb2[tid+o]; }
            __syncthreads();
        }
        coss[b] = sd[0] / (fmaxf(sqrtf(sa[0]), 1e-8f) * fmaxf(sqrtf(sb2[0]), 1e-8f));
        __syncthreads();
    }
    if (tid == 0) out[0] = 1.f - 0.5f*(coss[0] + coss[1]);
}

// ---------------- launch ----------------
extern "C" void kernel_launch(void* const* d_in, const int* in_sizes, int n_in,
                              void* d_out, int out_size) {
    const float* pred   = (const float*)d_in[0];
    const int*   tru    = (const int*)  d_in[1];
    const float* patchw = (const float*)d_in[2];
    const float* patchb = (const float*)d_in[3];
    const float* cls    = (const float*)d_in[4];
    const float* pos    = (const float*)d_in[5];
    const float* ln1g   = (const float*)d_in[6];
    const float* ln1b   = (const float*)d_in[7];
    const float* qkvw   = (const float*)d_in[8];
    const float* qkvb   = (const float*)d_in[9];
    const float* projw  = (const float*)d_in[10];
    const float* projb  = (const float*)d_in[11];
    const float* ln2g   = (const float*)d_in[12];
    const float* ln2b   = (const float*)d_in[13];
    const float* fc1w   = (const float*)d_in[14];
    const float* fc1b   = (const float*)d_in[15];
    const float* fc2w   = (const float*)d_in[16];
    const float* fc2b   = (const float*)d_in[17];
    const float* normg  = (const float*)d_in[18];
    const float* normb  = (const float*)d_in[19];

    float *px, *ph, *ptok, *ppart;
    cudaGetSymbolAddress((void**)&px,    d_x);
    cudaGetSymbolAddress((void**)&ph,    d_h);
    cudaGetSymbolAddress((void**)&ptok,  d_tok);
    cudaGetSymbolAddress((void**)&ppart, d_part);

    __half *h0,*h1,*a0,*a1,*m0,*m1,*p0,*p1,*qk0,*qk1;
    __half *ws0,*ws1,*q0,*q1,*pr0,*pr1,*f10,*f11,*f20,*f21;
    cudaGetSymbolAddress((void**)&h0, d_h0);   cudaGetSymbolAddress((void**)&h1, d_h1);
    cudaGetSymbolAddress((void**)&a0, d_a0);   cudaGetSymbolAddress((void**)&a1, d_a1);
    cudaGetSymbolAddress((void**)&m0, d_m0);   cudaGetSymbolAddress((void**)&m1, d_m1);
    cudaGetSymbolAddress((void**)&p0, d_p0);   cudaGetSymbolAddress((void**)&p1, d_p1);
    cudaGetSymbolAddress((void**)&qk0, d_q0);  cudaGetSymbolAddress((void**)&qk1, d_q1);
    cudaGetSymbolAddress((void**)&ws0, d_ws0); cudaGetSymbolAddress((void**)&ws1, d_ws1);
    cudaGetSymbolAddress((void**)&q0, d_qT0);  cudaGetSymbolAddress((void**)&q1, d_qT1);
    cudaGetSymbolAddress((void**)&pr0, d_pT0); cudaGetSymbolAddress((void**)&pr1, d_pT1);
    cudaGetSymbolAddress((void**)&f10, d_f1T0); cudaGetSymbolAddress((void**)&f11, d_f1T1);
    cudaGetSymbolAddress((void**)&f20, d_f2T0); cudaGetSymbolAddress((void**)&f21, d_f2T1);

    cudaFuncSetAttribute(k_g64, cudaFuncAttributeMaxDynamicSharedMemorySize, SMEM_G64);
    cudaFuncSetAttribute(k_scores_h, cudaFuncAttributeMaxDynamicSharedMemorySize, SMEM_SC);
    cudaFuncSetAttribute(k_av_h,     cudaFuncAttributeMaxDynamicSharedMemorySize, SMEM_AV);

    const float INV_W = 1.f/(AS*WS);
    const float INV_P = 1.f/(PS*WS);

    // front sequence
    k_edt_row<<<(NIMG*IH+127)/128, 128>>>(pred, tru);
    k_edt_col<<<(NIMG*NPIX+255)/256, 256>>>();
    k_wsumT  <<<(DM*256+255)/256, 256>>>(patchw);
    k_g64<<<dim3(DM/128, (NIMG*NPATCH)/128), 512, SMEM_G64>>>(
        p0, p1, ws0, ws1, patchb, nullptr, ptok, nullptr, nullptr,
        NIMG*NPATCH, DM, 256, 256, INV_P, 0);
    k_assemble<<<(BT*DM+255)/256, 256>>>(cls, pos);

    // weight prep
    k_tsplit<<<dim3(2304/32, DM/32, NL),  dim3(32,8)>>>(qkvw,  q0, q1, DM,   2304);
    k_tsplit<<<dim3(DM/32,   DM/32, NL),  dim3(32,8)>>>(projw, pr0, pr1, DM, DM);
    k_tsplit<<<dim3(3072/32, DM/32, NL),  dim3(32,8)>>>(fc1w,  f10, f11, DM, 3072);
    k_tsplit<<<dim3(DM/32, 3072/32, NL),  dim3(32,8)>>>(fc2w,  f20, f21, 3072, DM);

    int MT = (BT + 127) / 128;   // 19
    int R4 = (BT*DM/4 + 255) / 256;

    // layer-0 ln1
    k_ln<<<BT, 256>>>(px, ln1g, ln1b);

    for (int l = 0; l < NL; l++) {
        k_g64<<<dim3(2304/128, MT), 512, SMEM_G64>>>(
            h0, h1, q0 + (size_t)l*2304*DM, q1 + (size_t)l*2304*DM,
            qkvb + (size_t)l*2304, nullptr, nullptr, qk0, qk1,
            BT, 2304, DM, DM, INV_W, 3);
        k_scores_h<<<dim3(5, 5, NIMG*NHD), 256, SMEM_SC>>>();
        k_rowstat <<<NIMG*NHD*NT, 128>>>();
        k_av_h    <<<dim3(5, NIMG*NHD), 256, SMEM_AV>>>();
        // proj: split-K 2 -> fused reduce + residual + ln2
        k_g64<<<dim3(DM/128, MT, 2), 512, SMEM_G64>>>(
            a0, a1, pr0 + (size_t)l*DM*DM, pr1 + (size_t)l*DM*DM,
            nullptr, nullptr, ppart, nullptr, nullptr,
            BT, DM, 384, 768, INV_W, 4);
        k_redln<<<BT, 256>>>(ppart, 2, INV_W, projb + (size_t)l*DM, px,
                             ln2g + (size_t)l*DM, ln2b + (size_t)l*DM);
        k_g64<<<dim3(3072/128, MT), 512, SMEM_G64>>>(
            h0, h1, f10 + (size_t)l*3072*DM, f11 + (size_t)l*3072*DM,
            fc1b + (size_t)l*3072, nullptr, nullptr, m0, m1,
            BT, 3072, DM, DM, INV_W, 1);
        // fc2: split-K 4 -> fused reduce + residual + next ln1 (or plain last)
        k_g64<<<dim3(DM/128, MT, 4), 512, SMEM_G64>>>(
            m0, m1, f20 + (size_t)l*DM*3072, f21 + (size_t)l*DM*3072,
            nullptr, nullptr, ppart, nullptr, nullptr,
            BT, DM, 768, 3072, INV_W, 4);
        if (l + 1 < NL) {
            k_redln<<<BT, 256>>>(ppart, 4, INV_W, fc2b + (size_t)l*DM, px,
                                 ln1g + (size_t)(l+1)*DM, ln1b + (size_t)(l+1)*DM);
        } else {
            k_red<<<R4, 256>>>(ppart, 4, INV_W, fc2b + (size_t)l*DM, px, px,
                               DM, BT*DM/4);
        }
    }

    k_lncls<<<NIMG, 256>>>(px, ph, normg, normb);
    k_loss<<<1, 256>>>((float*)d_out);
}

// round 15
// speedup vs baseline: 1.1340x; 1.1340x over previous
#include <cuda_runtime.h>
#include <cuda_fp16.h>
#include <math.h>
#include <stdint.h>

// ---------------- problem constants ----------------
#define IH 384
#define IW 384
#define NPIX (IH*IW)
#define NIMG 4
#define NT 577
#define DM 768
#define NL 12
#define NHD 12
#define BT (NIMG*NT)    // 2308
#define NPATCH 576
#define BIGF 1e4f
#define SPF 640

// static scales
#define WS  4096.f
#define AS  256.f
#define PS  32.f
#define SS  256.f

// ---------------- scratch ----------------
__device__ float d_g2fg[NIMG*NPIX];
__device__ float d_g2bg[NIMG*NPIX];
__device__ float d_tok [NIMG*NPATCH*DM];
__device__ float d_x   [BT*DM];
__device__ float d_h   [BT*DM];
__device__ __align__(128) float d_S[(size_t)NIMG*NHD*NT*SPF];
__device__ float2 d_rs [NIMG*NHD*NT];
__device__ float d_part[(size_t)4*BT*DM];

__device__ __align__(128) __half d_h0[BT*DM],    d_h1[BT*DM];
__device__ __align__(128) __half d_a0[BT*DM],    d_a1[BT*DM];
__device__ __align__(128) __half d_m0[BT*3072],  d_m1[BT*3072];
__device__ __align__(128) __half d_p0[NIMG*NPATCH*256], d_p1[NIMG*NPATCH*256];
__device__ __align__(128) __half d_q0[BT*3*DM],  d_q1[BT*3*DM];

__device__ __align__(128) __half d_ws0[DM*256],       d_ws1[DM*256];
__device__ __align__(128) __half d_qT0[NL*2304*DM],   d_qT1[NL*2304*DM];
__device__ __align__(128) __half d_pT0[NL*DM*DM],     d_pT1[NL*DM*DM];
__device__ __align__(128) __half d_f1T0[NL*3072*DM],  d_f1T1[NL*3072*DM];
__device__ __align__(128) __half d_f2T0[NL*DM*3072],  d_f2T1[NL*DM*3072];

// ---------------- helpers ----------------
__device__ __forceinline__ void split2h(float x, float s, __half& h0, __half& h1) {
    float xs = x * s;
    h0 = __float2half_rn(xs);
    h1 = __float2half_rn(xs - __half2float(h0));
}
__device__ __forceinline__ uint32_t s2u(const void* p) {
    uint32_t a;
    asm("{ .reg .u64 t; cvta.to.shared.u64 t, %1; cvt.u32.u64 %0, t; }" : "=r"(a) : "l"(p));
    return a;
}
#define CP16(s,g)  asm volatile("cp.async.cg.shared.global [%0], [%1], 16;" :: "r"(s), "l"(g))
#define CPCOMMIT() asm volatile("cp.async.commit_group;")
#define CPWAIT0()  asm volatile("cp.async.wait_group 0;")

__device__ __forceinline__ void ldsm4(unsigned &r0, unsigned &r1, unsigned &r2,
                                      unsigned &r3, uint32_t addr) {
    asm volatile("ldmatrix.sync.aligned.m8n8.x4.shared.b16 {%0,%1,%2,%3}, [%4];"
        : "=r"(r0), "=r"(r1), "=r"(r2), "=r"(r3) : "r"(addr));
}
__device__ __forceinline__ void ldsm4t(unsigned &r0, unsigned &r1, unsigned &r2,
                                       unsigned &r3, uint32_t addr) {
    asm volatile("ldmatrix.sync.aligned.m8n8.x4.trans.shared.b16 {%0,%1,%2,%3}, [%4];"
        : "=r"(r0), "=r"(r1), "=r"(r2), "=r"(r3) : "r"(addr));
}
#define MMA_F16(c, a, b0v, b1v) \
    asm volatile("mma.sync.aligned.m16n8k16.row.col.f32.f16.f16.f32 " \
                 "{%0,%1,%2,%3},{%4,%5,%6,%7},{%8,%9},{%0,%1,%2,%3};" \
                 : "+f"((c)[0]), "+f"((c)[1]), "+f"((c)[2]), "+f"((c)[3]) \
                 : "r"((a)[0]), "r"((a)[1]), "r"((a)[2]), "r"((a)[3]), \
                   "r"(b0v), "r"(b1v))

// ---------------- EDT row pass (mask fused) ----------------
__global__ void k_edt_row(const float* __restrict__ logits, const int* __restrict__ tr) {
    int idx = blockIdx.x*blockDim.x + threadIdx.x;
    if (idx >= NIMG*IH) return;
    int img = idx / IH, i = idx % IH;
    float* gf = d_g2fg + (size_t)img*NPIX + (size_t)i*IW;
    float* gb = d_g2bg + (size_t)img*NPIX + (size_t)i*IW;
    const float* l0p = logits + ((size_t)img*2)*NPIX + (size_t)i*IW;
    const float* l1p = l0p + NPIX;
    const int*   trp = tr + (size_t)(img-2)*NPIX + (size_t)i*IW;
    bool islog = (img < 2);

    float lf = -BIGF, lb = -BIGF;
    for (int j = 0; j < IW; j++) {
        bool mz = islog ? !(l1p[j] > l0p[j]) : (trp[j] == 0);
        float jj = (float)j;
        if (mz) lf = jj; else lb = jj;
        gf[j] = jj - lf;
        gb[j] = jj - lb;
    }
    float rf = BIGF, rb = BIGF;
    for (int j = IW-1; j >= 0; j--) {
        bool mz = islog ? !(l1p[j] > l0p[j]) : (trp[j] == 0);
        float jj = (float)j;
        if (mz) rf = jj; else rb = jj;
        float g1 = fminf(fminf(gf[j], rf - jj), BIGF);
        float g2 = fminf(fminf(gb[j], rb - jj), BIGF);
        gf[j] = g1*g1;
        gb[j] = g2*g2;
    }
}

// ---------------- EDT column pass + SDM + patch-split write ----------------
__global__ void k_edt_col() {
    int idx = blockIdx.x*blockDim.x + threadIdx.x;
    if (idx >= NIMG*NPIX) return;
    int img = idx / NPIX, r = idx % NPIX;
    int i = r / IW, j = r % IW;
    const float* gf = d_g2fg + (size_t)img*NPIX;
    const float* gb = d_g2bg + (size_t)img*NPIX;
    float mf = 3.4e38f, mb = 3.4e38f;
    float fi = (float)i;
    for (int ii = 0; ii < IH; ii++) {
        float off = fi - (float)ii; off *= off;
        mf = fminf(mf, gf[(size_t)ii*IW + j] + off);
        mb = fminf(mb, gb[(size_t)ii*IW + j] + off);
    }
    float v = sqrtf(mb) - sqrtf(mf);
    int t = (i >> 4)*24 + (j >> 4);
    int k = ((i & 15) << 4) + (j & 15);
    size_t o = (size_t)img*NPATCH*256 + (size_t)t*256 + k;
    split2h(v, PS, d_p0[o], d_p1[o]);
}

// ---------------- weight prep ----------------
__global__ void k_wsumT(const float* __restrict__ pw) {
    int idx = blockIdx.x*blockDim.x + threadIdx.x;
    if (idx >= DM*256) return;
    int o = idx / 256, k = idx % 256;
    float v = pw[(size_t)k*DM + o] + pw[(size_t)(256+k)*DM + o] + pw[(size_t)(512+k)*DM + o];
    split2h(v, WS, d_ws0[idx], d_ws1[idx]);
}

__global__ void k_tsplit(const float* __restrict__ W, __half* __restrict__ T0,
                         __half* __restrict__ T1, int K, int N) {
    __shared__ float t[32][33];
    size_t off = (size_t)blockIdx.z * K * N;
    const float* w = W + off;
    int bx = blockIdx.x*32, by = blockIdx.y*32;
    int tx = threadIdx.x, ty = threadIdx.y;
    #pragma unroll
    for (int r = 0; r < 4; r++)
        t[ty + r*8][tx] = w[(size_t)(by + ty + r*8)*N + bx + tx];
    __syncthreads();
    #pragma unroll
    for (int r = 0; r < 4; r++) {
        int n = bx + ty + r*8, k = by + tx;
        float v = t[tx][ty + r*8];
        size_t o = off + (size_t)n*K + k;
        split2h(v, WS, T0[o], T1[o]);
    }
}

__global__ void k_assemble(const float* __restrict__ cls, const float* __restrict__ pos) {
    int idx = blockIdx.x*blockDim.x + threadIdx.x;
    if (idx >= BT*DM) return;
    int img = idx / (NT*DM);
    int rem = idx % (NT*DM);
    int t = rem / DM, c = rem % DM;
    float v = (t == 0) ? cls[c] : d_tok[((size_t)img*NPATCH + (t-1))*DM + c];
    d_x[idx] = v + pos[(size_t)t*DM + c];
}

// ---------------- layernorm (split planes only) ----------------
__global__ void k_ln(const float* __restrict__ in,
                     const float* __restrict__ g, const float* __restrict__ b) {
    int row = blockIdx.x;
    int tid = threadIdx.x;
    const float* xr = in + (size_t)row*DM;
    __shared__ float red[256];
    float v[3];
    #pragma unroll
    for (int i = 0; i < 3; i++) v[i] = xr[tid + i*256];
    float s = v[0] + v[1] + v[2];
    red[tid] = s; __syncthreads();
    for (int o = 128; o > 0; o >>= 1) { if (tid < o) red[tid] += red[tid+o]; __syncthreads(); }
    float mu = red[0] * (1.f/768.f);
    __syncthreads();
    float var = 0.f;
    #pragma unroll
    for (int i = 0; i < 3; i++) { float dd = v[i]-mu; var += dd*dd; }
    red[tid] = var; __syncthreads();
    for (int o = 128; o > 0; o >>= 1) { if (tid < o) red[tid] += red[tid+o]; __syncthreads(); }
    float rstd = rsqrtf(red[0] * (1.f/768.f) + 1e-6f);
    #pragma unroll
    for (int i = 0; i < 3; i++) {
        int c = tid + i*256;
        float val = (v[i]-mu)*rstd*g[c] + b[c];
        size_t o = (size_t)row*DM + c;
        split2h(val, AS, d_h0[o], d_h1[o]);
    }
}

// ---------------- fused split-K reduce + residual + LN + split write --------
__global__ void k_redln(const float* __restrict__ P, int ns, float inv,
                        const float* __restrict__ bias, float* __restrict__ x,
                        const float* __restrict__ g, const float* __restrict__ b) {
    int row = blockIdx.x;
    int tid = threadIdx.x;
    __shared__ float red[256];
    const size_t MN = (size_t)BT*DM;
    float v[3];
    #pragma unroll
    for (int i = 0; i < 3; i++) {
        int c = tid + i*256;
        size_t o = (size_t)row*DM + c;
        float s = P[o];
        for (int z = 1; z < ns; z++) s += P[(size_t)z*MN + o];
        v[i] = s*inv + bias[c] + x[o];
        x[o] = v[i];
    }
    float s = v[0] + v[1] + v[2];
    red[tid] = s; __syncthreads();
    for (int o = 128; o > 0; o >>= 1) { if (tid < o) red[tid] += red[tid+o]; __syncthreads(); }
    float mu = red[0] * (1.f/768.f);
    __syncthreads();
    float var = 0.f;
    #pragma unroll
    for (int i = 0; i < 3; i++) { float dd = v[i]-mu; var += dd*dd; }
    red[tid] = var; __syncthreads();
    for (int o = 128; o > 0; o >>= 1) { if (tid < o) red[tid] += red[tid+o]; __syncthreads(); }
    float rstd = rsqrtf(red[0] * (1.f/768.f) + 1e-6f);
    #pragma unroll
    for (int i = 0; i < 3; i++) {
        int c = tid + i*256;
        float val = (v[i]-mu)*rstd*g[c] + b[c];
        size_t o = (size_t)row*DM + c;
        split2h(val, AS, d_h0[o], d_h1[o]);
    }
}

// ---------------- final LN on the 4 cls rows only ----------------
__global__ void k_lncls(const float* __restrict__ in, float* __restrict__ out,
                        const float* __restrict__ g, const float* __restrict__ b) {
    int row = blockIdx.x * NT;
    int tid = threadIdx.x;
    const float* xr = in + (size_t)row*DM;
    __shared__ float red[256];
    float v[3];
    #pragma unroll
    for (int i = 0; i < 3; i++) v[i] = xr[tid + i*256];
    float s = v[0] + v[1] + v[2];
    red[tid] = s; __syncthreads();
    for (int o = 128; o > 0; o >>= 1) { if (tid < o) red[tid] += red[tid+o]; __syncthreads(); }
    float mu = red[0] * (1.f/768.f);
    __syncthreads();
    float var = 0.f;
    #pragma unroll
    for (int i = 0; i < 3; i++) { float dd = v[i]-mu; var += dd*dd; }
    red[tid] = var; __syncthreads();
    for (int o = 128; o > 0; o >>= 1) { if (tid < o) red[tid] += red[tid+o]; __syncthreads(); }
    float rstd = rsqrtf(red[0] * (1.f/768.f) + 1e-6f);
    #pragma unroll
    for (int i = 0; i < 3; i++) {
        int c = tid + i*256;
        out[(size_t)row*DM + c] = (v[i]-mu)*rstd*g[c] + b[c];
    }
}

// ---------------- shared epilogue ----------------
__device__ __forceinline__ void gemm_epilogue(
        float v0, float v1, int gr, int gc, int N, int epi,
        const float* res, float* C, __half* C0, __half* C1) {
    if (epi == 1 || epi == 3) {
        if (epi == 1) {
            v0 = 0.5f*v0*(1.f + erff(v0*0.70710678118654752f));
            v1 = 0.5f*v1*(1.f + erff(v1*0.70710678118654752f));
        }
        size_t o = (size_t)gr*N + gc;
        __half h00, h01, h10, h11;
        split2h(v0, AS, h00, h01);
        split2h(v1, AS, h10, h11);
        __half2 p0; p0.x = h00; p0.y = h10;
        __half2 p1; p1.x = h01; p1.y = h11;
        *(__half2*)&C0[o] = p0;
        *(__half2*)&C1[o] = p1;
    } else {
        if (epi == 2) {
            float2 r2 = *(const float2*)&res[(size_t)gr*N + gc];
            v0 += r2.x; v1 += r2.y;
        }
        *(float2*)&C[(size_t)gr*N + gc] = make_float2(v0, v1);
    }
}

// ================= GEMM A: 256 threads, 128x128 tile, optional split-K ======
#define APL 10240u
#define BPL128 10240u
#define BUFB128 (2u*APL + 2u*BPL128)
#define SMEM_GH (2u*BUFB128)

__global__ __launch_bounds__(256, 2) void k_gemm_h(
        const __half* __restrict__ A0, const __half* __restrict__ A1,
        const __half* __restrict__ B0, const __half* __restrict__ B1,
        const float* __restrict__ bias, const float* __restrict__ res,
        float* __restrict__ C, __half* __restrict__ C0, __half* __restrict__ C1,
        int M, int N, int K, int LDK, float inv, int epi) {
    extern __shared__ char smem[];
    uint32_t sb = s2u(smem);
    int tid = threadIdx.x, lane = tid & 31, warp = tid >> 5;
    int wm = (warp & 3)*32, wn = (warp >> 2)*64;
    int bm = blockIdx.y*128, bn = blockIdx.x*128;
    size_t koff = (size_t)blockIdx.z * K;
    int g = lane >> 2, q = lane & 3;

    float acc[2][8][4];
    #pragma unroll
    for (int i=0;i<2;i++)
        #pragma unroll
        for (int j=0;j<8;j++)
            #pragma unroll
            for (int r=0;r<4;r++) acc[i][j][r]=0.f;

    int lrow = tid >> 2;
    int lc   = tid & 3;

    auto load_chunk = [&](int kt, int buf) {
        int k0 = kt * 32;
        uint32_t base = sb + (uint32_t)buf * BUFB128;
        const __half* Ap[2] = {A0, A1};
        const __half* Bp[2] = {B0, B1};
        #pragma unroll
        for (int p = 0; p < 2; p++) {
            #pragma unroll
            for (int l = 0; l < 2; l++) {
                int row = lrow + l*64;
                int gr = bm + row; if (gr >= M) gr = M - 1;
                CP16(base + p*APL + (uint32_t)(row*80 + lc*16),
                     Ap[p] + (size_t)gr*LDK + koff + k0 + lc*8);
                CP16(base + 2*APL + p*BPL128 + (uint32_t)(row*80 + lc*16),
                     Bp[p] + (size_t)(bn + row)*LDK + koff + k0 + lc*8);
            }
        }
    };

    int KT = K >> 5;
    load_chunk(0, 0);
    CPCOMMIT();
    for (int kt = 0; kt < KT; kt++) {
        CPWAIT0();
        __syncthreads();
        if (kt + 1 < KT) { load_chunk(kt + 1, (kt + 1) & 1); CPCOMMIT(); }
        uint32_t base = sb + (uint32_t)(kt & 1) * BUFB128;
        uint32_t aBase = base + (uint32_t)((wm + (lane & 15))*80 + (lane >> 4)*16);
        int bn8 = (lane & 7) + ((lane >> 4) << 3);
        uint32_t bBase = base + 2*APL + (uint32_t)((wn + bn8)*80 + ((lane >> 3) & 1)*16);
        #pragma unroll
        for (int ks = 0; ks < 2; ks++) {
            unsigned a0f[2][4], a1f[2][4];
            #pragma unroll
            for (int mi = 0; mi < 2; mi++) {
                ldsm4(a0f[mi][0],a0f[mi][1],a0f[mi][2],a0f[mi][3],
                      aBase + mi*1280u + ks*32u);
                ldsm4(a1f[mi][0],a1f[mi][1],a1f[mi][2],a1f[mi][3],
                      aBase + APL + mi*1280u + ks*32u);
            }
            #pragma unroll
            for (int nq = 0; nq < 4; nq++) {
                unsigned b0f[4], b1f[4];
                ldsm4(b0f[0],b0f[1],b0f[2],b0f[3], bBase + nq*1280u + ks*32u);
                ldsm4(b1f[0],b1f[1],b1f[2],b1f[3], bBase + BPL128 + nq*1280u + ks*32u);
                #pragma unroll
                for (int mi = 0; mi < 2; mi++)
                    #pragma unroll
                    for (int h = 0; h < 2; h++) {
                        MMA_F16(acc[mi][nq*2+h], a0f[mi], b0f[h*2], b0f[h*2+1]);
                        MMA_F16(acc[mi][nq*2+h], a0f[mi], b1f[h*2], b1f[h*2+1]);
                        MMA_F16(acc[mi][nq*2+h], a1f[mi], b0f[h*2], b0f[h*2+1]);
                    }
            }
        }
    }
    __syncthreads();

    size_t pofs = (size_t)blockIdx.z * M * N;
    #pragma unroll
    for (int mi = 0; mi < 2; mi++)
        #pragma unroll
        for (int rr = 0; rr < 2; rr++) {
            int gr = bm + wm + mi*16 + g + rr*8;
            if (gr >= M) continue;
            #pragma unroll
            for (int nj = 0; nj < 8; nj++) {
                int gc = bn + wn + nj*8 + 2*q;
                if (epi == 4) {
                    *(float2*)&C[pofs + (size_t)gr*N + gc] =
                        make_float2(acc[mi][nj][rr*2+0], acc[mi][nj][rr*2+1]);
                } else {
                    gemm_epilogue(acc[mi][nj][rr*2+0]*inv + bias[gc],
                                  acc[mi][nj][rr*2+1]*inv + bias[gc+1],
                                  gr, gc, N, epi, res, C, C0, C1);
                }
            }
        }
}

// ---------------- split-K reduce (plain; last layer fc2) ----------------
__global__ void k_red(const float* __restrict__ P, int ns, float inv,
                      const float* __restrict__ bias, const float* __restrict__ res,
                      float* __restrict__ C, int N, int total4) {
    int t = blockIdx.x*blockDim.x + threadIdx.x;
    if (t >= total4) return;
    size_t i = (size_t)t * 4;
    size_t MN = (size_t)total4 * 4;
    float4 s = *(const float4*)&P[i];
    for (int z = 1; z < ns; z++) {
        float4 p = *(const float4*)&P[(size_t)z*MN + i];
        s.x += p.x; s.y += p.y; s.z += p.z; s.w += p.w;
    }
    int c = (int)(i % N);
    float4 b = *(const float4*)&bias[c];
    float4 r = *(const float4*)&res[i];
    s.x = s.x*inv + b.x + r.x;
    s.y = s.y*inv + b.y + r.y;
    s.z = s.z*inv + b.z + r.z;
    s.w = s.w*inv + b.w + r.w;
    *(float4*)&C[i] = s;
}

// ================= GEMM W: 512 threads, 128x128 tile (patch) ===============
__global__ __launch_bounds__(512, 1) void k_gemm_w(
        const __half* __restrict__ A0, const __half* __restrict__ A1,
        const __half* __restrict__ B0, const __half* __restrict__ B1,
        const float* __restrict__ bias, const float* __restrict__ res,
        float* __restrict__ C, __half* __restrict__ C0, __half* __restrict__ C1,
        int M, int N, int K, float inv, int epi) {
    extern __shared__ char smem[];
    uint32_t sb = s2u(smem);
    int tid = threadIdx.x, lane = tid & 31, warp = tid >> 5;
    int wm = (warp & 3)*32, wn = (warp >> 2)*32;
    int bm = blockIdx.y*128, bn = blockIdx.x*128;
    int g = lane >> 2, q = lane & 3;

    float acc[2][4][4];
    #pragma unroll
    for (int i=0;i<2;i++)
        #pragma unroll
        for (int j=0;j<4;j++)
            #pragma unroll
            for (int r=0;r<4;r++) acc[i][j][r]=0.f;

    int lrow = tid >> 2;
    int lc   = tid & 3;

    auto load_chunk = [&](int kt, int buf) {
        int k0 = kt * 32;
        uint32_t base = sb + (uint32_t)buf * BUFB128;
        const __half* Ap[2] = {A0, A1};
        const __half* Bp[2] = {B0, B1};
        int gr = bm + lrow; if (gr >= M) gr = M - 1;
        #pragma unroll
        for (int p = 0; p < 2; p++) {
            CP16(base + p*APL + (uint32_t)(lrow*80 + lc*16),
                 Ap[p] + (size_t)gr*K + k0 + lc*8);
            CP16(base + 2*APL + p*BPL128 + (uint32_t)(lrow*80 + lc*16),
                 Bp[p] + (size_t)(bn + lrow)*K + k0 + lc*8);
        }
    };

    int KT = K >> 5;
    load_chunk(0, 0);
    CPCOMMIT();
    for (int kt = 0; kt < KT; kt++) {
        CPWAIT0();
        __syncthreads();
        if (kt + 1 < KT) { load_chunk(kt + 1, (kt + 1) & 1); CPCOMMIT(); }
        uint32_t base = sb + (uint32_t)(kt & 1) * BUFB128;
        uint32_t aBase = base + (uint32_t)((wm + (lane & 15))*80 + (lane >> 4)*16);
        int bn8 = (lane & 7) + ((lane >> 4) << 3);
        uint32_t bBase = base + 2*APL + (uint32_t)((wn + bn8)*80 + ((lane >> 3) & 1)*16);
        #pragma unroll
        for (int ks = 0; ks < 2; ks++) {
            unsigned a0f[2][4], a1f[2][4];
            #pragma unroll
            for (int mi = 0; mi < 2; mi++) {
                ldsm4(a0f[mi][0],a0f[mi][1],a0f[mi][2],a0f[mi][3],
                      aBase + mi*1280u + ks*32u);
                ldsm4(a1f[mi][0],a1f[mi][1],a1f[mi][2],a1f[mi][3],
                      aBase + APL + mi*1280u + ks*32u);
            }
            #pragma unroll
            for (int nq = 0; nq < 2; nq++) {
                unsigned b0f[4], b1f[4];
                ldsm4(b0f[0],b0f[1],b0f[2],b0f[3], bBase + nq*1280u + ks*32u);
                ldsm4(b1f[0],b1f[1],b1f[2],b1f[3], bBase + BPL128 + nq*1280u + ks*32u);
                #pragma unroll
                for (int mi = 0; mi < 2; mi++)
                    #pragma unroll
                    for (int h = 0; h < 2; h++) {
                        MMA_F16(acc[mi][nq*2+h], a0f[mi], b0f[h*2], b0f[h*2+1]);
                        MMA_F16(acc[mi][nq*2+h], a0f[mi], b1f[h*2], b1f[h*2+1]);
                        MMA_F16(acc[mi][nq*2+h], a1f[mi], b0f[h*2], b0f[h*2+1]);
                    }
            }
        }
    }
    __syncthreads();

    #pragma unroll
    for (int mi = 0; mi < 2; mi++)
        #pragma unroll
        for (int rr = 0; rr < 2; rr++) {
            int gr = bm + wm + mi*16 + g + rr*8;
            if (gr >= M) continue;
            #pragma unroll
            for (int nj = 0; nj < 4; nj++) {
                int gc = bn + wn + nj*8 + 2*q;
                gemm_epilogue(acc[mi][nj][rr*2+0]*inv + bias[gc],
                              acc[mi][nj][rr*2+1]*inv + bias[gc+1],
                              gr, gc, N, epi, res, C, C0, C1);
            }
        }
}

// ================= attention scores (fp32 out, padded stride SPF) ===========
#define SROW 144u
#define SPL  (128u*SROW)
#define SMEM_SC (4u*SPL)

__global__ __launch_bounds__(256, 2) void k_scores_h() {
    extern __shared__ char smem[];
    uint32_t sb = s2u(smem);
    int bh = blockIdx.z, b = bh / NHD, h = bh % NHD;
    int m0 = blockIdx.y*128, n0 = blockIdx.x*128;
    int tid = threadIdx.x, lane = tid & 31, warp = tid >> 5;
    int wm = (warp & 3)*32, wn = (warp >> 2)*64;
    int g = lane >> 2, q = lane & 3;

    #pragma unroll
    for (int l = 0; l < 4; l++) {
        int id = tid + l*256;
        int row = id >> 3, c = id & 7;
        int gm = m0 + row; if (gm >= NT) gm = NT - 1;
        int gn = n0 + row; if (gn >= NT) gn = NT - 1;
        size_t qo = (size_t)(b*NT + gm)*2304 + h*64 + c*8;
        size_t ko = (size_t)(b*NT + gn)*2304 + 768 + h*64 + c*8;
        uint32_t so = (uint32_t)(row*SROW + c*16);
        CP16(sb + so,          d_q0 + qo);
        CP16(sb + SPL + so,    d_q1 + qo);
        CP16(sb + 2*SPL + so,  d_q0 + ko);
        CP16(sb + 3*SPL + so,  d_q1 + ko);
    }
    CPCOMMIT(); CPWAIT0();
    __syncthreads();

    float acc[2][8][4];
    #pragma unroll
    for (int i=0;i<2;i++)
        #pragma unroll
        for (int j=0;j<8;j++)
            #pragma unroll
            for (int r=0;r<4;r++) acc[i][j][r]=0.f;

    uint32_t aBase = sb + (uint32_t)((wm + (lane & 15))*SROW + (lane >> 4)*16);
    int bn8 = (lane & 7) + ((lane >> 4) << 3);
    uint32_t bBase = sb + 2*SPL + (uint32_t)((wn + bn8)*SROW + ((lane >> 3) & 1)*16);

    #pragma unroll
    for (int ks = 0; ks < 4; ks++) {
        unsigned a0f[2][4], a1f[2][4];
        #pragma unroll
        for (int mi = 0; mi < 2; mi++) {
            ldsm4(a0f[mi][0],a0f[mi][1],a0f[mi][2],a0f[mi][3],
                  aBase + mi*16*SROW + ks*32u);
            ldsm4(a1f[mi][0],a1f[mi][1],a1f[mi][2],a1f[mi][3],
                  aBase + SPL + mi*16*SROW + ks*32u);
        }
        #pragma unroll
        for (int nq = 0; nq < 4; nq++) {
            unsigned b0f[4], b1f[4];
            ldsm4(b0f[0],b0f[1],b0f[2],b0f[3], bBase + nq*16*SROW + ks*32u);
            ldsm4(b1f[0],b1f[1],b1f[2],b1f[3], bBase + SPL + nq*16*SROW + ks*32u);
            #pragma unroll
            for (int mi = 0; mi < 2; mi++)
                #pragma unroll
                for (int hh = 0; hh < 2; hh++) {
                    MMA_F16(acc[mi][nq*2+hh], a0f[mi], b0f[hh*2], b0f[hh*2+1]);
                    MMA_F16(acc[mi][nq*2+hh], a0f[mi], b1f[hh*2], b1f[hh*2+1]);
                    MMA_F16(acc[mi][nq*2+hh], a1f[mi], b0f[hh*2], b0f[hh*2+1]);
                }
        }
    }

    const float SCL = 0.125f/(AS*AS);
    float* sbase = d_S + (size_t)bh*NT*SPF;
    #pragma unroll
    for (int mi = 0; mi < 2; mi++)
        #pragma unroll
        for (int rr = 0; rr < 2; rr++) {
            int gm = m0 + wm + mi*16 + g + rr*8;
            if (gm >= NT) continue;
            #pragma unroll
            for (int nj = 0; nj < 8; nj++) {
                int gc = n0 + wn + nj*8 + 2*q;
                if (gc < NT)   sbase[(size_t)gm*SPF + gc]   = acc[mi][nj][rr*2+0]*SCL;
                if (gc+1 < NT) sbase[(size_t)gm*SPF + gc+1] = acc[mi][nj][rr*2+1]*SCL;
            }
        }
}

// ---------------- row stats ----------------
__global__ void k_rowstat() {
    size_t row = blockIdx.x;
    const float* s = d_S + row*SPF;
    int tid = threadIdx.x;
    __shared__ float red[128];
    float v[5];
    float mx = -3.4e38f;
    #pragma unroll
    for (int i = 0; i < 5; i++) {
        int c = tid + i*128;
        v[i] = (c < NT) ? s[c] : -3.4e38f;
        mx = fmaxf(mx, v[i]);
    }
    red[tid] = mx; __syncthreads();
    for (int o = 64; o > 0; o >>= 1) { if (tid < o) red[tid] = fmaxf(red[tid], red[tid+o]); __syncthreads(); }
    mx = red[0]; __syncthreads();
    float sum = 0.f;
    #pragma unroll
    for (int i = 0; i < 5; i++) sum += __expf(v[i] - mx);
    red[tid] = sum; __syncthreads();
    for (int o = 64; o > 0; o >>= 1) { if (tid < o) red[tid] += red[tid+o]; __syncthreads(); }
    if (tid == 0) d_rs[row] = make_float2(mx, SS / red[0]);
}

// ================= AV: fused exp/normalize + split + MMA ====================
#define AV_RS   0u
#define AV_P0   1024u
#define AV_P1   11264u
#define AV_BUF0 21504u
#define AV_FB   18432u
#define AV_VPL  4608u
#define AV_BUFSZ (AV_FB + 2u*AV_VPL)
#define SMEM_AV (AV_BUF0 + 2u*AV_BUFSZ)

__global__ __launch_bounds__(256, 2) void k_av_h() {
    extern __shared__ char smem[];
    uint32_t sb = s2u(smem);
    int bh = blockIdx.y, b = bh / NHD, h = bh % NHD;
    int m0 = blockIdx.x*128;
    int tid = threadIdx.x, lane = tid & 31, warp = tid >> 5;
    int wm = (warp & 3)*32, wn = (warp >> 2)*32;
    int g = lane >> 2, q = lane & 3;

    float acc[2][4][4];
    #pragma unroll
    for (int i=0;i<2;i++)
        #pragma unroll
        for (int j=0;j<4;j++)
            #pragma unroll
            for (int r=0;r<4;r++) acc[i][j][r]=0.f;

    const float* Sf = d_S + (size_t)bh*NT*SPF;

    if (tid < 128) {
        int gm = m0 + tid; if (gm >= NT) gm = NT - 1;
        *(float2*)(smem + AV_RS + tid*8) = d_rs[(size_t)bh*NT + gm];
    }

    auto load_chunk = [&](int kt, int buf) {
        int k0 = kt * 32;
        uint32_t base = sb + AV_BUF0 + (uint32_t)buf * AV_BUFSZ;
        #pragma unroll
        for (int l = 0; l < 4; l++) {
            int id = tid + l*256;
            int row = id >> 3, c = id & 7;
            int gm = m0 + row; if (gm >= NT) gm = NT - 1;
            CP16(base + (uint32_t)(row*144 + c*16),
                 Sf + (size_t)gm*SPF + k0 + c*4);
        }
        {
            int row = tid >> 3, c = tid & 7;
            int gk = k0 + row; if (gk >= NT) gk = NT - 1;
            size_t vo = (size_t)(b*NT + gk)*2304 + 1536 + h*64 + c*8;
            uint32_t d = (uint32_t)(row*144 + c*16);
            CP16(base + AV_FB + d,           d_q0 + vo);
            CP16(base + AV_FB + AV_VPL + d,  d_q1 + vo);
        }
    };

    const int KT = (NT + 31) / 32;   // 19
    load_chunk(0, 0);
    CPCOMMIT();
    for (int kt = 0; kt < KT; kt++) {
        int buf = kt & 1;
        int k0 = kt * 32;
        CPWAIT0();
        __syncthreads();
        if (kt + 1 < KT) { load_chunk(kt + 1, (kt + 1) & 1); CPCOMMIT(); }
        {
            int row = tid >> 1, colh = (tid & 1)*16;
            float2 ri = *(const float2*)(smem + AV_RS + row*8);
            const float* F = (const float*)(smem + AV_BUF0 + buf*AV_BUFSZ) + row*36 + colh;
            char* P0w = smem + AV_P0 + row*80 + colh*2;
            char* P1w = smem + AV_P1 + row*80 + colh*2;
            #pragma unroll
            for (int j = 0; j < 16; j += 2) {
                int k = k0 + colh + j;
                float f0 = F[j], f1 = F[j+1];
                float p0 = (k     < NT) ? __expf(f0 - ri.x)*ri.y : 0.f;
                float p1 = (k + 1 < NT) ? __expf(f1 - ri.x)*ri.y : 0.f;
                __half a0h = __float2half_rn(p0);
                __half b0h = __float2half_rn(p1);
                __half a1h = __float2half_rn(p0 - __half2float(a0h));
                __half b1h = __float2half_rn(p1 - __half2float(b0h));
                __half2 w0; w0.x = a0h; w0.y = b0h;
                __half2 w1; w1.x = a1h; w1.y = b1h;
                *(__half2*)(P0w + j*2) = w0;
                *(__half2*)(P1w + j*2) = w1;
            }
        }
        __syncthreads();
        uint32_t aBase = sb + AV_P0 + (uint32_t)((wm + (lane & 15))*80 + (lane >> 4)*16);
        uint32_t vb0 = sb + AV_BUF0 + (uint32_t)buf*AV_BUFSZ + AV_FB;
        uint32_t bBase = vb0 + (uint32_t)((lane & 15)*144 + wn*2 + (lane >> 4)*16);
        #pragma unroll
        for (int ks = 0; ks < 2; ks++) {
            unsigned a0f[2][4], a1f[2][4];
            #pragma unroll
            for (int mi = 0; mi < 2; mi++) {
                ldsm4(a0f[mi][0],a0f[mi][1],a0f[mi][2],a0f[mi][3],
                      aBase + mi*16*80u + ks*32u);
                ldsm4(a1f[mi][0],a1f[mi][1],a1f[mi][2],a1f[mi][3],
                      aBase + (AV_P1 - AV_P0) + mi*16*80u + ks*32u);
            }
            #pragma unroll
            for (int nq = 0; nq < 2; nq++) {
                unsigned b0f[4], b1f[4];
                uint32_t ba = bBase + ks*16*144u + nq*32u;
                ldsm4t(b0f[0],b0f[1],b0f[2],b0f[3], ba);
                ldsm4t(b1f[0],b1f[1],b1f[2],b1f[3], ba + AV_VPL);
                #pragma unroll
                for (int mi = 0; mi < 2; mi++)
                    #pragma unroll
                    for (int hh = 0; hh < 2; hh++) {
                        MMA_F16(acc[mi][nq*2+hh], a0f[mi], b0f[hh*2], b0f[hh*2+1]);
                        MMA_F16(acc[mi][nq*2+hh], a0f[mi], b1f[hh*2], b1f[hh*2+1]);
                        MMA_F16(acc[mi][nq*2+hh], a1f[mi], b0f[hh*2], b0f[hh*2+1]);
                    }
            }
        }
    }

    const float INV_AV = 1.f/(SS*AS);
    #pragma unroll
    for (int mi = 0; mi < 2; mi++)
        #pragma unroll
        for (int rr = 0; rr < 2; rr++) {
            int gm = m0 + wm + mi*16 + g + rr*8;
            if (gm >= NT) continue;
            #pragma unroll
            for (int nj = 0; nj < 4; nj++) {
                int gc = wn + nj*8 + 2*q;
                size_t o = (size_t)(b*NT + gm)*DM + h*64 + gc;
                float v0 = acc[mi][nj][rr*2+0]*INV_AV;
                float v1 = acc[mi][nj][rr*2+1]*INV_AV;
                __half h00, h01, h10, h11;
                split2h(v0, AS, h00, h01);
                split2h(v1, AS, h10, h11);
                __half2 p0; p0.x = h00; p0.y = h10;
                __half2 p1; p1.x = h01; p1.y = h11;
                *(__half2*)&d_a0[o] = p0;
                *(__half2*)&d_a1[o] = p1;
            }
        }
}

// ---------------- final cosine loss ----------------
__global__ void k_loss(float* out) {
    __shared__ float sd[256], sa[256], sb2[256];
    int tid = threadIdx.x;
    float coss[2];
    for (int b = 0; b < 2; b++) {
        const float* fp = d_h + (size_t)b*NT*DM;
        const float* ft = d_h + (size_t)(2+b)*NT*DM;
        float dt = 0.f, na = 0.f, nb = 0.f;
        for (int c = tid; c < DM; c += 256) {
            float a = fp[c], bb = ft[c];
            dt += a*bb; na += a*a; nb += bb*bb;
        }
        sd[tid] = dt; sa[tid] = na; sb2[tid] = nb; __syncthreads();
        for (int o = 128; o > 0; o >>= 1) {
            if (tid < o) { sd[tid]+=sd[tid+o]; sa[tid]+=sa[tid+o]; sb2[tid]+=sb2[tid+o]; }
            __syncthreads();
        }
        coss[b] = sd[0] / (fmaxf(sqrtf(sa[0]), 1e-8f) * fmaxf(sqrtf(sb2[0]), 1e-8f));
        __syncthreads();
    }
    if (tid == 0) out[0] = 1.f - 0.5f*(coss[0] + coss[1]);
}

// ---------------- launch ----------------
extern "C" void kernel_launch(void* const* d_in, const int* in_sizes, int n_in,
                              void* d_out, int out_size) {
    const float* pred   = (const float*)d_in[0];
    const int*   tru    = (const int*)  d_in[1];
    const float* patchw = (const float*)d_in[2];
    const float* patchb = (const float*)d_in[3];
    const float* cls    = (const float*)d_in[4];
    const float* pos    = (const float*)d_in[5];
    const float* ln1g   = (const float*)d_in[6];
    const float* ln1b   = (const float*)d_in[7];
    const float* qkvw   = (const float*)d_in[8];
    const float* qkvb   = (const float*)d_in[9];
    const float* projw  = (const float*)d_in[10];
    const float* projb  = (const float*)d_in[11];
    const float* ln2g   = (const float*)d_in[12];
    const float* ln2b   = (const float*)d_in[13];
    const float* fc1w   = (const float*)d_in[14];
    const float* fc1b   = (const float*)d_in[15];
    const float* fc2w   = (const float*)d_in[16];
    const float* fc2b   = (const float*)d_in[17];
    const float* normg  = (const float*)d_in[18];
    const float* normb  = (const float*)d_in[19];

    float *px, *ph, *ptok, *ppart;
    cudaGetSymbolAddress((void**)&px,    d_x);
    cudaGetSymbolAddress((void**)&ph,    d_h);
    cudaGetSymbolAddress((void**)&ptok,  d_tok);
    cudaGetSymbolAddress((void**)&ppart, d_part);

    __half *h0,*h1,*a0,*a1,*m0,*m1,*p0,*p1,*qk0,*qk1;
    __half *ws0,*ws1,*q0,*q1,*pr0,*pr1,*f10,*f11,*f20,*f21;
    cudaGetSymbolAddress((void**)&h0, d_h0);   cudaGetSymbolAddress((void**)&h1, d_h1);
    cudaGetSymbolAddress((void**)&a0, d_a0);   cudaGetSymbolAddress((void**)&a1, d_a1);
    cudaGetSymbolAddress((void**)&m0, d_m0);   cudaGetSymbolAddress((void**)&m1, d_m1);
    cudaGetSymbolAddress((void**)&p0, d_p0);   cudaGetSymbolAddress((void**)&p1, d_p1);
    cudaGetSymbolAddress((void**)&qk0, d_q0);  cudaGetSymbolAddress((void**)&qk1, d_q1);
    cudaGetSymbolAddress((void**)&ws0, d_ws0); cudaGetSymbolAddress((void**)&ws1, d_ws1);
    cudaGetSymbolAddress((void**)&q0, d_qT0);  cudaGetSymbolAddress((void**)&q1, d_qT1);
    cudaGetSymbolAddress((void**)&pr0, d_pT0); cudaGetSymbolAddress((void**)&pr1, d_pT1);
    cudaGetSymbolAddress((void**)&f10, d_f1T0); cudaGetSymbolAddress((void**)&f11, d_f1T1);
    cudaGetSymbolAddress((void**)&f20, d_f2T0); cudaGetSymbolAddress((void**)&f21, d_f2T1);

    cudaFuncSetAttribute(k_gemm_h, cudaFuncAttributeMaxDynamicSharedMemorySize, SMEM_GH);
    cudaFuncSetAttribute(k_gemm_w, cudaFuncAttributeMaxDynamicSharedMemorySize, SMEM_GH);
    cudaFuncSetAttribute(k_scores_h, cudaFuncAttributeMaxDynamicSharedMemorySize, SMEM_SC);
    cudaFuncSetAttribute(k_av_h,     cudaFuncAttributeMaxDynamicSharedMemorySize, SMEM_AV);

    const float INV_W = 1.f/(AS*WS);
    const float INV_P = 1.f/(PS*WS);

    // front sequence
    k_edt_row<<<(NIMG*IH+127)/128, 128>>>(pred, tru);
    k_edt_col<<<(NIMG*NPIX+255)/256, 256>>>();
    k_wsumT  <<<(DM*256+255)/256, 256>>>(patchw);
    k_gemm_w<<<dim3(DM/128, (NIMG*NPATCH)/128), 512, SMEM_GH>>>(
        p0, p1, ws0, ws1, patchb, nullptr, ptok, nullptr, nullptr,
        NIMG*NPATCH, DM, 256, INV_P, 0);
    k_assemble<<<(BT*DM+255)/256, 256>>>(cls, pos);

    // weight prep
    k_tsplit<<<dim3(2304/32, DM/32, NL),  dim3(32,8)>>>(qkvw,  q0, q1, DM,   2304);
    k_tsplit<<<dim3(DM/32,   DM/32, NL),  dim3(32,8)>>>(projw, pr0, pr1, DM, DM);
    k_tsplit<<<dim3(3072/32, DM/32, NL),  dim3(32,8)>>>(fc1w,  f10, f11, DM, 3072);
    k_tsplit<<<dim3(DM/32, 3072/32, NL),  dim3(32,8)>>>(fc2w,  f20, f21, 3072, DM);

    int MT = (BT + 127) / 128;   // 19
    int R4 = (BT*DM/4 + 255) / 256;

    // layer-0 ln1
    k_ln<<<BT, 256>>>(px, ln1g, ln1b);

    for (int l = 0; l < NL; l++) {
        k_gemm_h<<<dim3(2304/128, MT), 256, SMEM_GH>>>(
            h0, h1, q0 + (size_t)l*2304*DM, q1 + (size_t)l*2304*DM,
            qkvb + (size_t)l*2304, nullptr, nullptr, qk0, qk1,
            BT, 2304, DM, DM, INV_W, 3);
        k_scores_h<<<dim3(5, 5, NIMG*NHD), 256, SMEM_SC>>>();
        k_rowstat <<<NIMG*NHD*NT, 128>>>();
        k_av_h    <<<dim3(5, NIMG*NHD), 256, SMEM_AV>>>();
        // proj: split-K 2 -> fused reduce + residual + ln2
        k_gemm_h<<<dim3(DM/128, MT, 2), 256, SMEM_GH>>>(
            a0, a1, pr0 + (size_t)l*DM*DM, pr1 + (size_t)l*DM*DM,
            nullptr, nullptr, ppart, nullptr, nullptr,
            BT, DM, 384, 768, INV_W, 4);
        k_redln<<<BT, 256>>>(ppart, 2, INV_W, projb + (size_t)l*DM, px,
                             ln2g + (size_t)l*DM, ln2b + (size_t)l*DM);
        k_gemm_h<<<dim3(3072/128, MT), 256, SMEM_GH>>>(
            h0, h1, f10 + (size_t)l*3072*DM, f11 + (size_t)l*3072*DM,
            fc1b + (size_t)l*3072, nullptr, nullptr, m0, m1,
            BT, 3072, DM, DM, INV_W, 1);
        // fc2: split-K 4 -> fused reduce + residual + next ln1 (or plain last)
        k_gemm_h<<<dim3(DM/128, MT, 4), 256, SMEM_GH>>>(
            m0, m1, f20 + (size_t)l*DM*3072, f21 + (size_t)l*DM*3072,
            nullptr, nullptr, ppart, nullptr, nullptr,
            BT, DM, 768, 3072, INV_W, 4);
        if (l + 1 < NL) {
            k_redln<<<BT, 256>>>(ppart, 4, INV_W, fc2b + (size_t)l*DM, px,
                                 ln1g + (size_t)(l+1)*DM, ln1b + (size_t)(l+1)*DM);
        } else {
            k_red<<<R4, 256>>>(ppart, 4, INV_W, fc2b + (size_t)l*DM, px, px,
                               DM, BT*DM/4);
        }
    }

    k_lncls<<<NIMG, 256>>>(px, ph, normg, normb);
    k_loss<<<1, 256>>>((float*)d_out);
}

// round 16
// speedup vs baseline: 1.1793x; 1.0399x over previous
#include <cuda_runtime.h>
#include <cuda_fp16.h>
#include <math.h>
#include <stdint.h>

// ---------------- problem constants ----------------
#define IH 384
#define IW 384
#define NPIX (IH*IW)
#define NIMG 4
#define NT 577
#define DM 768
#define NL 12
#define NHD 12
#define BT (NIMG*NT)    // 2308
#define NPATCH 576
#define BIGF 1e4f
#define SPF 640

// static scales
#define WS  4096.f
#define AS  256.f
#define PS  32.f
#define SS  256.f

// ---------------- scratch ----------------
__device__ float d_g2fg[NIMG*NPIX];
__device__ float d_g2bg[NIMG*NPIX];
__device__ float d_tok [NIMG*NPATCH*DM];
__device__ float d_x   [BT*DM];
__device__ float d_h   [BT*DM];
__device__ __align__(128) float d_S[(size_t)NIMG*NHD*NT*SPF];
__device__ float2 d_rs [NIMG*NHD*NT];
__device__ float2 d_ps [(size_t)NIMG*NHD*NT*5];   // per-tile (max, expsum)
__device__ float d_part[(size_t)4*BT*DM];

__device__ __align__(128) __half d_h0[BT*DM],    d_h1[BT*DM];
__device__ __align__(128) __half d_a0[BT*DM],    d_a1[BT*DM];
__device__ __align__(128) __half d_m0[BT*3072],  d_m1[BT*3072];
__device__ __align__(128) __half d_p0[NIMG*NPATCH*256], d_p1[NIMG*NPATCH*256];
__device__ __align__(128) __half d_q0[BT*3*DM],  d_q1[BT*3*DM];

__device__ __align__(128) __half d_ws0[DM*256],       d_ws1[DM*256];
__device__ __align__(128) __half d_qT0[NL*2304*DM],   d_qT1[NL*2304*DM];
__device__ __align__(128) __half d_pT0[NL*DM*DM],     d_pT1[NL*DM*DM];
__device__ __align__(128) __half d_f1T0[NL*3072*DM],  d_f1T1[NL*3072*DM];
__device__ __align__(128) __half d_f2T0[NL*DM*3072],  d_f2T1[NL*DM*3072];

// ---------------- helpers ----------------
__device__ __forceinline__ void split2h(float x, float s, __half& h0, __half& h1) {
    float xs = x * s;
    h0 = __float2half_rn(xs);
    h1 = __float2half_rn(xs - __half2float(h0));
}
__device__ __forceinline__ uint32_t s2u(const void* p) {
    uint32_t a;
    asm("{ .reg .u64 t; cvta.to.shared.u64 t, %1; cvt.u32.u64 %0, t; }" : "=r"(a) : "l"(p));
    return a;
}
#define CP16(s,g)  asm volatile("cp.async.cg.shared.global [%0], [%1], 16;" :: "r"(s), "l"(g))
#define CPCOMMIT() asm volatile("cp.async.commit_group;")
#define CPWAIT0()  asm volatile("cp.async.wait_group 0;")

__device__ __forceinline__ void ldsm4(unsigned &r0, unsigned &r1, unsigned &r2,
                                      unsigned &r3, uint32_t addr) {
    asm volatile("ldmatrix.sync.aligned.m8n8.x4.shared.b16 {%0,%1,%2,%3}, [%4];"
        : "=r"(r0), "=r"(r1), "=r"(r2), "=r"(r3) : "r"(addr));
}
__device__ __forceinline__ void ldsm4t(unsigned &r0, unsigned &r1, unsigned &r2,
                                       unsigned &r3, uint32_t addr) {
    asm volatile("ldmatrix.sync.aligned.m8n8.x4.trans.shared.b16 {%0,%1,%2,%3}, [%4];"
        : "=r"(r0), "=r"(r1), "=r"(r2), "=r"(r3) : "r"(addr));
}
#define MMA_F16(c, a, b0v, b1v) \
    asm volatile("mma.sync.aligned.m16n8k16.row.col.f32.f16.f16.f32 " \
                 "{%0,%1,%2,%3},{%4,%5,%6,%7},{%8,%9},{%0,%1,%2,%3};" \
                 : "+f"((c)[0]), "+f"((c)[1]), "+f"((c)[2]), "+f"((c)[3]) \
                 : "r"((a)[0]), "r"((a)[1]), "r"((a)[2]), "r"((a)[3]), \
                   "r"(b0v), "r"(b1v))

// ---------------- EDT row pass (mask fused) ----------------
__global__ void k_edt_row(const float* __restrict__ logits, const int* __restrict__ tr) {
    int idx = blockIdx.x*blockDim.x + threadIdx.x;
    if (idx >= NIMG*IH) return;
    int img = idx / IH, i = idx % IH;
    float* gf = d_g2fg + (size_t)img*NPIX + (size_t)i*IW;
    float* gb = d_g2bg + (size_t)img*NPIX + (size_t)i*IW;
    const float* l0p = logits + ((size_t)img*2)*NPIX + (size_t)i*IW;
    const float* l1p = l0p + NPIX;
    const int*   trp = tr + (size_t)(img-2)*NPIX + (size_t)i*IW;
    bool islog = (img < 2);

    float lf = -BIGF, lb = -BIGF;
    for (int j = 0; j < IW; j++) {
        bool mz = islog ? !(l1p[j] > l0p[j]) : (trp[j] == 0);
        float jj = (float)j;
        if (mz) lf = jj; else lb = jj;
        gf[j] = jj - lf;
        gb[j] = jj - lb;
    }
    float rf = BIGF, rb = BIGF;
    for (int j = IW-1; j >= 0; j--) {
        bool mz = islog ? !(l1p[j] > l0p[j]) : (trp[j] == 0);
        float jj = (float)j;
        if (mz) rf = jj; else rb = jj;
        float g1 = fminf(fminf(gf[j], rf - jj), BIGF);
        float g2 = fminf(fminf(gb[j], rb - jj), BIGF);
        gf[j] = g1*g1;
        gb[j] = g2*g2;
    }
}

// ---------------- EDT column pass + SDM + patch-split write ----------------
__global__ void k_edt_col() {
    int idx = blockIdx.x*blockDim.x + threadIdx.x;
    if (idx >= NIMG*NPIX) return;
    int img = idx / NPIX, r = idx % NPIX;
    int i = r / IW, j = r % IW;
    const float* gf = d_g2fg + (size_t)img*NPIX;
    const float* gb = d_g2bg + (size_t)img*NPIX;
    float mf = 3.4e38f, mb = 3.4e38f;
    float fi = (float)i;
    for (int ii = 0; ii < IH; ii++) {
        float off = fi - (float)ii; off *= off;
        mf = fminf(mf, gf[(size_t)ii*IW + j] + off);
        mb = fminf(mb, gb[(size_t)ii*IW + j] + off);
    }
    float v = sqrtf(mb) - sqrtf(mf);
    int t = (i >> 4)*24 + (j >> 4);
    int k = ((i & 15) << 4) + (j & 15);
    size_t o = (size_t)img*NPATCH*256 + (size_t)t*256 + k;
    split2h(v, PS, d_p0[o], d_p1[o]);
}

// ---------------- weight prep ----------------
__global__ void k_wsumT(const float* __restrict__ pw) {
    int idx = blockIdx.x*blockDim.x + threadIdx.x;
    if (idx >= DM*256) return;
    int o = idx / 256, k = idx % 256;
    float v = pw[(size_t)k*DM + o] + pw[(size_t)(256+k)*DM + o] + pw[(size_t)(512+k)*DM + o];
    split2h(v, WS, d_ws0[idx], d_ws1[idx]);
}

__global__ void k_tsplit(const float* __restrict__ W, __half* __restrict__ T0,
                         __half* __restrict__ T1, int K, int N) {
    __shared__ float t[32][33];
    size_t off = (size_t)blockIdx.z * K * N;
    const float* w = W + off;
    int bx = blockIdx.x*32, by = blockIdx.y*32;
    int tx = threadIdx.x, ty = threadIdx.y;
    #pragma unroll
    for (int r = 0; r < 4; r++)
        t[ty + r*8][tx] = w[(size_t)(by + ty + r*8)*N + bx + tx];
    __syncthreads();
    #pragma unroll
    for (int r = 0; r < 4; r++) {
        int n = bx + ty + r*8, k = by + tx;
        float v = t[tx][ty + r*8];
        size_t o = off + (size_t)n*K + k;
        split2h(v, WS, T0[o], T1[o]);
    }
}

__global__ void k_assemble(const float* __restrict__ cls, const float* __restrict__ pos) {
    int idx = blockIdx.x*blockDim.x + threadIdx.x;
    if (idx >= BT*DM) return;
    int img = idx / (NT*DM);
    int rem = idx % (NT*DM);
    int t = rem / DM, c = rem % DM;
    float v = (t == 0) ? cls[c] : d_tok[((size_t)img*NPATCH + (t-1))*DM + c];
    d_x[idx] = v + pos[(size_t)t*DM + c];
}

// ---------------- layernorm (split planes only) ----------------
__global__ void k_ln(const float* __restrict__ in,
                     const float* __restrict__ g, const float* __restrict__ b) {
    int row = blockIdx.x;
    int tid = threadIdx.x;
    const float* xr = in + (size_t)row*DM;
    __shared__ float red[256];
    float v[3];
    #pragma unroll
    for (int i = 0; i < 3; i++) v[i] = xr[tid + i*256];
    float s = v[0] + v[1] + v[2];
    red[tid] = s; __syncthreads();
    for (int o = 128; o > 0; o >>= 1) { if (tid < o) red[tid] += red[tid+o]; __syncthreads(); }
    float mu = red[0] * (1.f/768.f);
    __syncthreads();
    float var = 0.f;
    #pragma unroll
    for (int i = 0; i < 3; i++) { float dd = v[i]-mu; var += dd*dd; }
    red[tid] = var; __syncthreads();
    for (int o = 128; o > 0; o >>= 1) { if (tid < o) red[tid] += red[tid+o]; __syncthreads(); }
    float rstd = rsqrtf(red[0] * (1.f/768.f) + 1e-6f);
    #pragma unroll
    for (int i = 0; i < 3; i++) {
        int c = tid + i*256;
        float val = (v[i]-mu)*rstd*g[c] + b[c];
        size_t o = (size_t)row*DM + c;
        split2h(val, AS, d_h0[o], d_h1[o]);
    }
}

// ---------------- fused split-K reduce + residual + LN + split write --------
__global__ void k_redln(const float* __restrict__ P, int ns, float inv,
                        const float* __restrict__ bias, float* __restrict__ x,
                        const float* __restrict__ g, const float* __restrict__ b) {
    int row = blockIdx.x;
    int tid = threadIdx.x;
    __shared__ float red[256];
    const size_t MN = (size_t)BT*DM;
    float v[3];
    #pragma unroll
    for (int i = 0; i < 3; i++) {
        int c = tid + i*256;
        size_t o = (size_t)row*DM + c;
        float s = P[o];
        for (int z = 1; z < ns; z++) s += P[(size_t)z*MN + o];
        v[i] = s*inv + bias[c] + x[o];
        x[o] = v[i];
    }
    float s = v[0] + v[1] + v[2];
    red[tid] = s; __syncthreads();
    for (int o = 128; o > 0; o >>= 1) { if (tid < o) red[tid] += red[tid+o]; __syncthreads(); }
    float mu = red[0] * (1.f/768.f);
    __syncthreads();
    float var = 0.f;
    #pragma unroll
    for (int i = 0; i < 3; i++) { float dd = v[i]-mu; var += dd*dd; }
    red[tid] = var; __syncthreads();
    for (int o = 128; o > 0; o >>= 1) { if (tid < o) red[tid] += red[tid+o]; __syncthreads(); }
    float rstd = rsqrtf(red[0] * (1.f/768.f) + 1e-6f);
    #pragma unroll
    for (int i = 0; i < 3; i++) {
        int c = tid + i*256;
        float val = (v[i]-mu)*rstd*g[c] + b[c];
        size_t o = (size_t)row*DM + c;
        split2h(val, AS, d_h0[o], d_h1[o]);
    }
}

// ---------------- final LN on the 4 cls rows only ----------------
__global__ void k_lncls(const float* __restrict__ in, float* __restrict__ out,
                        const float* __restrict__ g, const float* __restrict__ b) {
    int row = blockIdx.x * NT;
    int tid = threadIdx.x;
    const float* xr = in + (size_t)row*DM;
    __shared__ float red[256];
    float v[3];
    #pragma unroll
    for (int i = 0; i < 3; i++) v[i] = xr[tid + i*256];
    float s = v[0] + v[1] + v[2];
    red[tid] = s; __syncthreads();
    for (int o = 128; o > 0; o >>= 1) { if (tid < o) red[tid] += red[tid+o]; __syncthreads(); }
    float mu = red[0] * (1.f/768.f);
    __syncthreads();
    float var = 0.f;
    #pragma unroll
    for (int i = 0; i < 3; i++) { float dd = v[i]-mu; var += dd*dd; }
    red[tid] = var; __syncthreads();
    for (int o = 128; o > 0; o >>= 1) { if (tid < o) red[tid] += red[tid+o]; __syncthreads(); }
    float rstd = rsqrtf(red[0] * (1.f/768.f) + 1e-6f);
    #pragma unroll
    for (int i = 0; i < 3; i++) {
        int c = tid + i*256;
        out[(size_t)row*DM + c] = (v[i]-mu)*rstd*g[c] + b[c];
    }
}

// ---------------- shared epilogue ----------------
__device__ __forceinline__ void gemm_epilogue(
        float v0, float v1, int gr, int gc, int N, int epi,
        const float* res, float* C, __half* C0, __half* C1) {
    if (epi == 1 || epi == 3) {
        if (epi == 1) {
            v0 = 0.5f*v0*(1.f + erff(v0*0.70710678118654752f));
            v1 = 0.5f*v1*(1.f + erff(v1*0.70710678118654752f));
        }
        size_t o = (size_t)gr*N + gc;
        __half h00, h01, h10, h11;
        split2h(v0, AS, h00, h01);
        split2h(v1, AS, h10, h11);
        __half2 p0; p0.x = h00; p0.y = h10;
        __half2 p1; p1.x = h01; p1.y = h11;
        *(__half2*)&C0[o] = p0;
        *(__half2*)&C1[o] = p1;
    } else {
        if (epi == 2) {
            float2 r2 = *(const float2*)&res[(size_t)gr*N + gc];
            v0 += r2.x; v1 += r2.y;
        }
        *(float2*)&C[(size_t)gr*N + gc] = make_float2(v0, v1);
    }
}

// ================= GEMM A: 256 threads, 128x128 tile, optional split-K ======
#define APL 10240u
#define BPL128 10240u
#define BUFB128 (2u*APL + 2u*BPL128)
#define SMEM_GH (2u*BUFB128)

__global__ __launch_bounds__(256, 2) void k_gemm_h(
        const __half* __restrict__ A0, const __half* __restrict__ A1,
        const __half* __restrict__ B0, const __half* __restrict__ B1,
        const float* __restrict__ bias, const float* __restrict__ res,
        float* __restrict__ C, __half* __restrict__ C0, __half* __restrict__ C1,
        int M, int N, int K, int LDK, float inv, int epi) {
    extern __shared__ char smem[];
    uint32_t sb = s2u(smem);
    int tid = threadIdx.x, lane = tid & 31, warp = tid >> 5;
    int wm = (warp & 3)*32, wn = (warp >> 2)*64;
    int bm = blockIdx.y*128, bn = blockIdx.x*128;
    size_t koff = (size_t)blockIdx.z * K;
    int g = lane >> 2, q = lane & 3;

    float acc[2][8][4];
    #pragma unroll
    for (int i=0;i<2;i++)
        #pragma unroll
        for (int j=0;j<8;j++)
            #pragma unroll
            for (int r=0;r<4;r++) acc[i][j][r]=0.f;

    int lrow = tid >> 2;
    int lc   = tid & 3;

    auto load_chunk = [&](int kt, int buf) {
        int k0 = kt * 32;
        uint32_t base = sb + (uint32_t)buf * BUFB128;
        const __half* Ap[2] = {A0, A1};
        const __half* Bp[2] = {B0, B1};
        #pragma unroll
        for (int p = 0; p < 2; p++) {
            #pragma unroll
            for (int l = 0; l < 2; l++) {
                int row = lrow + l*64;
                int gr = bm + row; if (gr >= M) gr = M - 1;
                CP16(base + p*APL + (uint32_t)(row*80 + lc*16),
                     Ap[p] + (size_t)gr*LDK + koff + k0 + lc*8);
                CP16(base + 2*APL + p*BPL128 + (uint32_t)(row*80 + lc*16),
                     Bp[p] + (size_t)(bn + row)*LDK + koff + k0 + lc*8);
            }
        }
    };

    int KT = K >> 5;
    load_chunk(0, 0);
    CPCOMMIT();
    for (int kt = 0; kt < KT; kt++) {
        CPWAIT0();
        __syncthreads();
        if (kt + 1 < KT) { load_chunk(kt + 1, (kt + 1) & 1); CPCOMMIT(); }
        uint32_t base = sb + (uint32_t)(kt & 1) * BUFB128;
        uint32_t aBase = base + (uint32_t)((wm + (lane & 15))*80 + (lane >> 4)*16);
        int bn8 = (lane & 7) + ((lane >> 4) << 3);
        uint32_t bBase = base + 2*APL + (uint32_t)((wn + bn8)*80 + ((lane >> 3) & 1)*16);
        #pragma unroll
        for (int ks = 0; ks < 2; ks++) {
            unsigned a0f[2][4], a1f[2][4];
            #pragma unroll
            for (int mi = 0; mi < 2; mi++) {
                ldsm4(a0f[mi][0],a0f[mi][1],a0f[mi][2],a0f[mi][3],
                      aBase + mi*1280u + ks*32u);
                ldsm4(a1f[mi][0],a1f[mi][1],a1f[mi][2],a1f[mi][3],
                      aBase + APL + mi*1280u + ks*32u);
            }
            #pragma unroll
            for (int nq = 0; nq < 4; nq++) {
                unsigned b0f[4], b1f[4];
                ldsm4(b0f[0],b0f[1],b0f[2],b0f[3], bBase + nq*1280u + ks*32u);
                ldsm4(b1f[0],b1f[1],b1f[2],b1f[3], bBase + BPL128 + nq*1280u + ks*32u);
                #pragma unroll
                for (int mi = 0; mi < 2; mi++)
                    #pragma unroll
                    for (int h = 0; h < 2; h++) {
                        MMA_F16(acc[mi][nq*2+h], a0f[mi], b0f[h*2], b0f[h*2+1]);
                        MMA_F16(acc[mi][nq*2+h], a0f[mi], b1f[h*2], b1f[h*2+1]);
                        MMA_F16(acc[mi][nq*2+h], a1f[mi], b0f[h*2], b0f[h*2+1]);
                    }
            }
        }
    }
    __syncthreads();

    size_t pofs = (size_t)blockIdx.z * M * N;
    #pragma unroll
    for (int mi = 0; mi < 2; mi++)
        #pragma unroll
        for (int rr = 0; rr < 2; rr++) {
            int gr = bm + wm + mi*16 + g + rr*8;
            if (gr >= M) continue;
            #pragma unroll
            for (int nj = 0; nj < 8; nj++) {
                int gc = bn + wn + nj*8 + 2*q;
                if (epi == 4) {
                    *(float2*)&C[pofs + (size_t)gr*N + gc] =
                        make_float2(acc[mi][nj][rr*2+0], acc[mi][nj][rr*2+1]);
                } else {
                    gemm_epilogue(acc[mi][nj][rr*2+0]*inv + bias[gc],
                                  acc[mi][nj][rr*2+1]*inv + bias[gc+1],
                                  gr, gc, N, epi, res, C, C0, C1);
                }
            }
        }
}

// ---------------- split-K reduce (plain; last layer fc2) ----------------
__global__ void k_red(const float* __restrict__ P, int ns, float inv,
                      const float* __restrict__ bias, const float* __restrict__ res,
                      float* __restrict__ C, int N, int total4) {
    int t = blockIdx.x*blockDim.x + threadIdx.x;
    if (t >= total4) return;
    size_t i = (size_t)t * 4;
    size_t MN = (size_t)total4 * 4;
    float4 s = *(const float4*)&P[i];
    for (int z = 1; z < ns; z++) {
        float4 p = *(const float4*)&P[(size_t)z*MN + i];
        s.x += p.x; s.y += p.y; s.z += p.z; s.w += p.w;
    }
    int c = (int)(i % N);
    float4 b = *(const float4*)&bias[c];
    float4 r = *(const float4*)&res[i];
    s.x = s.x*inv + b.x + r.x;
    s.y = s.y*inv + b.y + r.y;
    s.z = s.z*inv + b.z + r.z;
    s.w = s.w*inv + b.w + r.w;
    *(float4*)&C[i] = s;
}

// ================= GEMM W: 512 threads, 128x128 tile (patch) ===============
__global__ __launch_bounds__(512, 1) void k_gemm_w(
        const __half* __restrict__ A0, const __half* __restrict__ A1,
        const __half* __restrict__ B0, const __half* __restrict__ B1,
        const float* __restrict__ bias, const float* __restrict__ res,
        float* __restrict__ C, __half* __restrict__ C0, __half* __restrict__ C1,
        int M, int N, int K, float inv, int epi) {
    extern __shared__ char smem[];
    uint32_t sb = s2u(smem);
    int tid = threadIdx.x, lane = tid & 31, warp = tid >> 5;
    int wm = (warp & 3)*32, wn = (warp >> 2)*32;
    int bm = blockIdx.y*128, bn = blockIdx.x*128;
    int g = lane >> 2, q = lane & 3;

    float acc[2][4][4];
    #pragma unroll
    for (int i=0;i<2;i++)
        #pragma unroll
        for (int j=0;j<4;j++)
            #pragma unroll
            for (int r=0;r<4;r++) acc[i][j][r]=0.f;

    int lrow = tid >> 2;
    int lc   = tid & 3;

    auto load_chunk = [&](int kt, int buf) {
        int k0 = kt * 32;
        uint32_t base = sb + (uint32_t)buf * BUFB128;
        const __half* Ap[2] = {A0, A1};
        const __half* Bp[2] = {B0, B1};
        int gr = bm + lrow; if (gr >= M) gr = M - 1;
        #pragma unroll
        for (int p = 0; p < 2; p++) {
            CP16(base + p*APL + (uint32_t)(lrow*80 + lc*16),
                 Ap[p] + (size_t)gr*K + k0 + lc*8);
            CP16(base + 2*APL + p*BPL128 + (uint32_t)(lrow*80 + lc*16),
                 Bp[p] + (size_t)(bn + lrow)*K + k0 + lc*8);
        }
    };

    int KT = K >> 5;
    load_chunk(0, 0);
    CPCOMMIT();
    for (int kt = 0; kt < KT; kt++) {
        CPWAIT0();
        __syncthreads();
        if (kt + 1 < KT) { load_chunk(kt + 1, (kt + 1) & 1); CPCOMMIT(); }
        uint32_t base = sb + (uint32_t)(kt & 1) * BUFB128;
        uint32_t aBase = base + (uint32_t)((wm + (lane & 15))*80 + (lane >> 4)*16);
        int bn8 = (lane & 7) + ((lane >> 4) << 3);
        uint32_t bBase = base + 2*APL + (uint32_t)((wn + bn8)*80 + ((lane >> 3) & 1)*16);
        #pragma unroll
        for (int ks = 0; ks < 2; ks++) {
            unsigned a0f[2][4], a1f[2][4];
            #pragma unroll
            for (int mi = 0; mi < 2; mi++) {
                ldsm4(a0f[mi][0],a0f[mi][1],a0f[mi][2],a0f[mi][3],
                      aBase + mi*1280u + ks*32u);
                ldsm4(a1f[mi][0],a1f[mi][1],a1f[mi][2],a1f[mi][3],
                      aBase + APL + mi*1280u + ks*32u);
            }
            #pragma unroll
            for (int nq = 0; nq < 2; nq++) {
                unsigned b0f[4], b1f[4];
                ldsm4(b0f[0],b0f[1],b0f[2],b0f[3], bBase + nq*1280u + ks*32u);
                ldsm4(b1f[0],b1f[1],b1f[2],b1f[3], bBase + BPL128 + nq*1280u + ks*32u);
                #pragma unroll
                for (int mi = 0; mi < 2; mi++)
                    #pragma unroll
                    for (int h = 0; h < 2; h++) {
                        MMA_F16(acc[mi][nq*2+h], a0f[mi], b0f[h*2], b0f[h*2+1]);
                        MMA_F16(acc[mi][nq*2+h], a0f[mi], b1f[h*2], b1f[h*2+1]);
                        MMA_F16(acc[mi][nq*2+h], a1f[mi], b0f[h*2], b0f[h*2+1]);
                    }
            }
        }
    }
    __syncthreads();

    #pragma unroll
    for (int mi = 0; mi < 2; mi++)
        #pragma unroll
        for (int rr = 0; rr < 2; rr++) {
            int gr = bm + wm + mi*16 + g + rr*8;
            if (gr >= M) continue;
            #pragma unroll
            for (int nj = 0; nj < 4; nj++) {
                int gc = bn + wn + nj*8 + 2*q;
                gemm_epilogue(acc[mi][nj][rr*2+0]*inv + bias[gc],
                              acc[mi][nj][rr*2+1]*inv + bias[gc+1],
                              gr, gc, N, epi, res, C, C0, C1);
            }
        }
}

// ================= attention scores + per-tile softmax stats =================
#define SROW 144u
#define SPL  (128u*SROW)
#define SMEM_SC (4u*SPL)

__global__ __launch_bounds__(256, 2) void k_scores_h() {
    extern __shared__ char smem[];
    uint32_t sb = s2u(smem);
    int bh = blockIdx.z, b = bh / NHD, h = bh % NHD;
    int m0 = blockIdx.y*128, n0 = blockIdx.x*128;
    int tid = threadIdx.x, lane = tid & 31, warp = tid >> 5;
    int wm = (warp & 3)*32, wn = (warp >> 2)*64;
    int g = lane >> 2, q = lane & 3;

    #pragma unroll
    for (int l = 0; l < 4; l++) {
        int id = tid + l*256;
        int row = id >> 3, c = id & 7;
        int gm = m0 + row; if (gm >= NT) gm = NT - 1;
        int gn = n0 + row; if (gn >= NT) gn = NT - 1;
        size_t qo = (size_t)(b*NT + gm)*2304 + h*64 + c*8;
        size_t ko = (size_t)(b*NT + gn)*2304 + 768 + h*64 + c*8;
        uint32_t so = (uint32_t)(row*SROW + c*16);
        CP16(sb + so,          d_q0 + qo);
        CP16(sb + SPL + so,    d_q1 + qo);
        CP16(sb + 2*SPL + so,  d_q0 + ko);
        CP16(sb + 3*SPL + so,  d_q1 + ko);
    }
    CPCOMMIT(); CPWAIT0();
    __syncthreads();

    float acc[2][8][4];
    #pragma unroll
    for (int i=0;i<2;i++)
        #pragma unroll
        for (int j=0;j<8;j++)
            #pragma unroll
            for (int r=0;r<4;r++) acc[i][j][r]=0.f;

    uint32_t aBase = sb + (uint32_t)((wm + (lane & 15))*SROW + (lane >> 4)*16);
    int bn8 = (lane & 7) + ((lane >> 4) << 3);
    uint32_t bBase = sb + 2*SPL + (uint32_t)((wn + bn8)*SROW + ((lane >> 3) & 1)*16);

    #pragma unroll
    for (int ks = 0; ks < 4; ks++) {
        unsigned a0f[2][4], a1f[2][4];
        #pragma unroll
        for (int mi = 0; mi < 2; mi++) {
            ldsm4(a0f[mi][0],a0f[mi][1],a0f[mi][2],a0f[mi][3],
                  aBase + mi*16*SROW + ks*32u);
            ldsm4(a1f[mi][0],a1f[mi][1],a1f[mi][2],a1f[mi][3],
                  aBase + SPL + mi*16*SROW + ks*32u);
        }
        #pragma unroll
        for (int nq = 0; nq < 4; nq++) {
            unsigned b0f[4], b1f[4];
            ldsm4(b0f[0],b0f[1],b0f[2],b0f[3], bBase + nq*16*SROW + ks*32u);
            ldsm4(b1f[0],b1f[1],b1f[2],b1f[3], bBase + SPL + nq*16*SROW + ks*32u);
            #pragma unroll
            for (int mi = 0; mi < 2; mi++)
                #pragma unroll
                for (int hh = 0; hh < 2; hh++) {
                    MMA_F16(acc[mi][nq*2+hh], a0f[mi], b0f[hh*2], b0f[hh*2+1]);
                    MMA_F16(acc[mi][nq*2+hh], a0f[mi], b1f[hh*2], b1f[hh*2+1]);
                    MMA_F16(acc[mi][nq*2+hh], a1f[mi], b0f[hh*2], b0f[hh*2+1]);
                }
        }
    }

    const float SCL = 0.125f/(AS*AS);
    float* sbase = d_S + (size_t)bh*NT*SPF;
    #pragma unroll
    for (int mi = 0; mi < 2; mi++)
        #pragma unroll
        for (int rr = 0; rr < 2; rr++) {
            int gm = m0 + wm + mi*16 + g + rr*8;
            if (gm >= NT) continue;
            #pragma unroll
            for (int nj = 0; nj < 8; nj++) {
                int gc = n0 + wn + nj*8 + 2*q;
                if (gc < NT)   sbase[(size_t)gm*SPF + gc]   = acc[mi][nj][rr*2+0]*SCL;
                if (gc+1 < NT) sbase[(size_t)gm*SPF + gc+1] = acc[mi][nj][rr*2+1]*SCL;
            }
        }

    // ---- per-tile softmax stats (flash partials): (max, expsum) per row ----
    __syncthreads();                         // all ldsm reads done; reuse smem
    float2* shst = (float2*)smem;            // [2][128] float2 = 2 KB
    #pragma unroll
    for (int mi = 0; mi < 2; mi++)
        #pragma unroll
        for (int rr = 0; rr < 2; rr++) {
            int rl = wm + mi*16 + g + rr*8;  // 0..127
            float vv[16];
            float mx = -3.4e38f;
            #pragma unroll
            for (int nj = 0; nj < 8; nj++) {
                int gc = n0 + wn + nj*8 + 2*q;
                float v0 = (gc   < NT) ? acc[mi][nj][rr*2+0]*SCL : -3.4e38f;
                float v1 = (gc+1 < NT) ? acc[mi][nj][rr*2+1]*SCL : -3.4e38f;
                vv[nj*2]   = v0;
                vv[nj*2+1] = v1;
                mx = fmaxf(mx, fmaxf(v0, v1));
            }
            mx = fmaxf(mx, __shfl_xor_sync(0xffffffffu, mx, 1));
            mx = fmaxf(mx, __shfl_xor_sync(0xffffffffu, mx, 2));
            float sm = 0.f;
            #pragma unroll
            for (int j = 0; j < 16; j++) sm += __expf(vv[j] - mx);
            sm += __shfl_xor_sync(0xffffffffu, sm, 1);
            sm += __shfl_xor_sync(0xffffffffu, sm, 2);
            if (q == 0) shst[(warp >> 2)*128 + rl] = make_float2(mx, sm);
        }
    __syncthreads();
    if (tid < 128) {
        float2 a2 = shst[tid], b2 = shst[128 + tid];
        float M = fmaxf(a2.x, b2.x);
        float S = a2.y*__expf(a2.x - M) + b2.y*__expf(b2.x - M);
        int gm = m0 + tid;
        if (gm < NT)
            d_ps[((size_t)bh*NT + gm)*5 + blockIdx.x] = make_float2(M, S);
    }
}

// ---------------- combine per-tile stats -> row stats ----------------
__global__ void k_combine() {
    int r = blockIdx.x*blockDim.x + threadIdx.x;
    if (r >= NIMG*NHD*NT) return;
    const float2* p = &d_ps[(size_t)r*5];
    float2 p0 = p[0], p1 = p[1], p2 = p[2], p3 = p[3], p4 = p[4];
    float M = fmaxf(fmaxf(fmaxf(p0.x, p1.x), fmaxf(p2.x, p3.x)), p4.x);
    float S = p0.y*__expf(p0.x - M) + p1.y*__expf(p1.x - M)
            + p2.y*__expf(p2.x - M) + p3.y*__expf(p3.x - M)
            + p4.y*__expf(p4.x - M);
    d_rs[r] = make_float2(M, SS / S);
}

// ================= AV: fused exp/normalize + split + MMA ====================
#define AV_RS   0u
#define AV_P0   1024u
#define AV_P1   11264u
#define AV_BUF0 21504u
#define AV_FB   18432u
#define AV_VPL  4608u
#define AV_BUFSZ (AV_FB + 2u*AV_VPL)
#define SMEM_AV (AV_BUF0 + 2u*AV_BUFSZ)

__global__ __launch_bounds__(256, 2) void k_av_h() {
    extern __shared__ char smem[];
    uint32_t sb = s2u(smem);
    int bh = blockIdx.y, b = bh / NHD, h = bh % NHD;
    int m0 = blockIdx.x*128;
    int tid = threadIdx.x, lane = tid & 31, warp = tid >> 5;
    int wm = (warp & 3)*32, wn = (warp >> 2)*32;
    int g = lane >> 2, q = lane & 3;

    float acc[2][4][4];
    #pragma unroll
    for (int i=0;i<2;i++)
        #pragma unroll
        for (int j=0;j<4;j++)
            #pragma unroll
            for (int r=0;r<4;r++) acc[i][j][r]=0.f;

    const float* Sf = d_S + (size_t)bh*NT*SPF;

    if (tid < 128) {
        int gm = m0 + tid; if (gm >= NT) gm = NT - 1;
        *(float2*)(smem + AV_RS + tid*8) = d_rs[(size_t)bh*NT + gm];
    }

    auto load_chunk = [&](int kt, int buf) {
        int k0 = kt * 32;
        uint32_t base = sb + AV_BUF0 + (uint32_t)buf * AV_BUFSZ;
        #pragma unroll
        for (int l = 0; l < 4; l++) {
            int id = tid + l*256;
            int row = id >> 3, c = id & 7;
            int gm = m0 + row; if (gm >= NT) gm = NT - 1;
            CP16(base + (uint32_t)(row*144 + c*16),
                 Sf + (size_t)gm*SPF + k0 + c*4);
        }
        {
            int row = tid >> 3, c = tid & 7;
            int gk = k0 + row; if (gk >= NT) gk = NT - 1;
            size_t vo = (size_t)(b*NT + gk)*2304 + 1536 + h*64 + c*8;
            uint32_t d = (uint32_t)(row*144 + c*16);
            CP16(base + AV_FB + d,           d_q0 + vo);
            CP16(base + AV_FB + AV_VPL + d,  d_q1 + vo);
        }
    };

    const int KT = (NT + 31) / 32;   // 19
    load_chunk(0, 0);
    CPCOMMIT();
    for (int kt = 0; kt < KT; kt++) {
        int buf = kt & 1;
        int k0 = kt * 32;
        CPWAIT0();
        __syncthreads();
        if (kt + 1 < KT) { load_chunk(kt + 1, (kt + 1) & 1); CPCOMMIT(); }
        {
            int row = tid >> 1, colh = (tid & 1)*16;
            float2 ri = *(const float2*)(smem + AV_RS + row*8);
            const float* F = (const float*)(smem + AV_BUF0 + buf*AV_BUFSZ) + row*36 + colh;
            char* P0w = smem + AV_P0 + row*80 + colh*2;
            char* P1w = smem + AV_P1 + row*80 + colh*2;
            #pragma unroll
            for (int j = 0; j < 16; j += 2) {
                int k = k0 + colh + j;
                float f0 = F[j], f1 = F[j+1];
                float p0 = (k     < NT) ? __expf(f0 - ri.x)*ri.y : 0.f;
                float p1 = (k + 1 < NT) ? __expf(f1 - ri.x)*ri.y : 0.f;
                __half a0h = __float2half_rn(p0);
                __half b0h = __float2half_rn(p1);
                __half a1h = __float2half_rn(p0 - __half2float(a0h));
                __half b1h = __float2half_rn(p1 - __half2float(b0h));
                __half2 w0; w0.x = a0h; w0.y = b0h;
                __half2 w1; w1.x = a1h; w1.y = b1h;
                *(__half2*)(P0w + j*2) = w0;
                *(__half2*)(P1w + j*2) = w1;
            }
        }
        __syncthreads();
        uint32_t aBase = sb + AV_P0 + (uint32_t)((wm + (lane & 15))*80 + (lane >> 4)*16);
        uint32_t vb0 = sb + AV_BUF0 + (uint32_t)buf*AV_BUFSZ + AV_FB;
        uint32_t bBase = vb0 + (uint32_t)((lane & 15)*144 + wn*2 + (lane >> 4)*16);
        #pragma unroll
        for (int ks = 0; ks < 2; ks++) {
            unsigned a0f[2][4], a1f[2][4];
            #pragma unroll
            for (int mi = 0; mi < 2; mi++) {
                ldsm4(a0f[mi][0],a0f[mi][1],a0f[mi][2],a0f[mi][3],
                      aBase + mi*16*80u + ks*32u);
                ldsm4(a1f[mi][0],a1f[mi][1],a1f[mi][2],a1f[mi][3],
                      aBase + (AV_P1 - AV_P0) + mi*16*80u + ks*32u);
            }
            #pragma unroll
            for (int nq = 0; nq < 2; nq++) {
                unsigned b0f[4], b1f[4];
                uint32_t ba = bBase + ks*16*144u + nq*32u;
                ldsm4t(b0f[0],b0f[1],b0f[2],b0f[3], ba);
                ldsm4t(b1f[0],b1f[1],b1f[2],b1f[3], ba + AV_VPL);
                #pragma unroll
                for (int mi = 0; mi < 2; mi++)
                    #pragma unroll
                    for (int hh = 0; hh < 2; hh++) {
                        MMA_F16(acc[mi][nq*2+hh], a0f[mi], b0f[hh*2], b0f[hh*2+1]);
                        MMA_F16(acc[mi][nq*2+hh], a0f[mi], b1f[hh*2], b1f[hh*2+1]);
                        MMA_F16(acc[mi][nq*2+hh], a1f[mi], b0f[hh*2], b0f[hh*2+1]);
                    }
            }
        }
    }

    const float INV_AV = 1.f/(SS*AS);
    #pragma unroll
    for (int mi = 0; mi < 2; mi++)
        #pragma unroll
        for (int rr = 0; rr < 2; rr++) {
            int gm = m0 + wm + mi*16 + g + rr*8;
            if (gm >= NT) continue;
            #pragma unroll
            for (int nj = 0; nj < 4; nj++) {
                int gc = wn + nj*8 + 2*q;
                size_t o = (size_t)(b*NT + gm)*DM + h*64 + gc;
                float v0 = acc[mi][nj][rr*2+0]*INV_AV;
                float v1 = acc[mi][nj][rr*2+1]*INV_AV;
                __half h00, h01, h10, h11;
                split2h(v0, AS, h00, h01);
                split2h(v1, AS, h10, h11);
                __half2 p0; p0.x = h00; p0.y = h10;
                __half2 p1; p1.x = h01; p1.y = h11;
                *(__half2*)&d_a0[o] = p0;
                *(__half2*)&d_a1[o] = p1;
            }
        }
}

// ---------------- final cosine loss ----------------
__global__ void k_loss(float* out) {
    __shared__ float sd[256], sa[256], sb2[256];
    int tid = threadIdx.x;
    float coss[2];
    for (int b = 0; b < 2; b++) {
        const float* fp = d_h + (size_t)b*NT*DM;
        const float* ft = d_h + (size_t)(2+b)*NT*DM;
        float dt = 0.f, na = 0.f, nb = 0.f;
        for (int c = tid; c < DM; c += 256) {
            float a = fp[c], bb = ft[c];
            dt += a*bb; na += a*a; nb += bb*bb;
        }
        sd[tid] = dt; sa[tid] = na; sb2[tid] = nb; __syncthreads();
        for (int o = 128; o > 0; o >>= 1) {
            if (tid < o) { sd[tid]+=sd[tid+o]; sa[tid]+=sa[tid+o]; sb2[tid]+=sb2[tid+o]; }
            __syncthreads();
        }
        coss[b] = sd[0] / (fmaxf(sqrtf(sa[0]), 1e-8f) * fmaxf(sqrtf(sb2[0]), 1e-8f));
        __syncthreads();
    }
    if (tid == 0) out[0] = 1.f - 0.5f*(coss[0] + coss[1]);
}

// ---------------- launch ----------------
extern "C" void kernel_launch(void* const* d_in, const int* in_sizes, int n_in,
                              void* d_out, int out_size) {
    const float* pred   = (const float*)d_in[0];
    const int*   tru    = (const int*)  d_in[1];
    const float* patchw = (const float*)d_in[2];
    const float* patchb = (const float*)d_in[3];
    const float* cls    = (const float*)d_in[4];
    const float* pos    = (const float*)d_in[5];
    const float* ln1g   = (const float*)d_in[6];
    const float* ln1b   = (const float*)d_in[7];
    const float* qkvw   = (const float*)d_in[8];
    const float* qkvb   = (const float*)d_in[9];
    const float* projw  = (const float*)d_in[10];
    const float* projb  = (const float*)d_in[11];
    const float* ln2g   = (const float*)d_in[12];
    const float* ln2b   = (const float*)d_in[13];
    const float* fc1w   = (const float*)d_in[14];
    const float* fc1b   = (const float*)d_in[15];
    const float* fc2w   = (const float*)d_in[16];
    const float* fc2b   = (const float*)d_in[17];
    const float* normg  = (const float*)d_in[18];
    const float* normb  = (const float*)d_in[19];

    float *px, *ph, *ptok, *ppart;
    cudaGetSymbolAddress((void**)&px,    d_x);
    cudaGetSymbolAddress((void**)&ph,    d_h);
    cudaGetSymbolAddress((void**)&ptok,  d_tok);
    cudaGetSymbolAddress((void**)&ppart, d_part);

    __half *h0,*h1,*a0,*a1,*m0,*m1,*p0,*p1,*qk0,*qk1;
    __half *ws0,*ws1,*q0,*q1,*pr0,*pr1,*f10,*f11,*f20,*f21;
    cudaGetSymbolAddress((void**)&h0, d_h0);   cudaGetSymbolAddress((void**)&h1, d_h1);
    cudaGetSymbolAddress((void**)&a0, d_a0);   cudaGetSymbolAddress((void**)&a1, d_a1);
    cudaGetSymbolAddress((void**)&m0, d_m0);   cudaGetSymbolAddress((void**)&m1, d_m1);
    cudaGetSymbolAddress((void**)&p0, d_p0);   cudaGetSymbolAddress((void**)&p1, d_p1);
    cudaGetSymbolAddress((void**)&qk0, d_q0);  cudaGetSymbolAddress((void**)&qk1, d_q1);
    cudaGetSymbolAddress((void**)&ws0, d_ws0); cudaGetSymbolAddress((void**)&ws1, d_ws1);
    cudaGetSymbolAddress((void**)&q0, d_qT0);  cudaGetSymbolAddress((void**)&q1, d_qT1);
    cudaGetSymbolAddress((void**)&pr0, d_pT0); cudaGetSymbolAddress((void**)&pr1, d_pT1);
    cudaGetSymbolAddress((void**)&f10, d_f1T0); cudaGetSymbolAddress((void**)&f11, d_f1T1);
    cudaGetSymbolAddress((void**)&f20, d_f2T0); cudaGetSymbolAddress((void**)&f21, d_f2T1);

    cudaFuncSetAttribute(k_gemm_h, cudaFuncAttributeMaxDynamicSharedMemorySize, SMEM_GH);
    cudaFuncSetAttribute(k_gemm_w, cudaFuncAttributeMaxDynamicSharedMemorySize, SMEM_GH);
    cudaFuncSetAttribute(k_scores_h, cudaFuncAttributeMaxDynamicSharedMemorySize, SMEM_SC);
    cudaFuncSetAttribute(k_av_h,     cudaFuncAttributeMaxDynamicSharedMemorySize, SMEM_AV);

    const float INV_W = 1.f/(AS*WS);
    const float INV_P = 1.f/(PS*WS);

    // front sequence
    k_edt_row<<<(NIMG*IH+127)/128, 128>>>(pred, tru);
    k_edt_col<<<(NIMG*NPIX+255)/256, 256>>>();
    k_wsumT  <<<(DM*256+255)/256, 256>>>(patchw);
    k_gemm_w<<<dim3(DM/128, (NIMG*NPATCH)/128), 512, SMEM_GH>>>(
        p0, p1, ws0, ws1, patchb, nullptr, ptok, nullptr, nullptr,
        NIMG*NPATCH, DM, 256, INV_P, 0);
    k_assemble<<<(BT*DM+255)/256, 256>>>(cls, pos);

    // weight prep
    k_tsplit<<<dim3(2304/32, DM/32, NL),  dim3(32,8)>>>(qkvw,  q0, q1, DM,   2304);
    k_tsplit<<<dim3(DM/32,   DM/32, NL),  dim3(32,8)>>>(projw, pr0, pr1, DM, DM);
    k_tsplit<<<dim3(3072/32, DM/32, NL),  dim3(32,8)>>>(fc1w,  f10, f11, DM, 3072);
    k_tsplit<<<dim3(DM/32, 3072/32, NL),  dim3(32,8)>>>(fc2w,  f20, f21, 3072, DM);

    int MT = (BT + 127) / 128;   // 19
    int R4 = (BT*DM/4 + 255) / 256;
    int NCMB = (NIMG*NHD*NT + 255) / 256;

    // layer-0 ln1
    k_ln<<<BT, 256>>>(px, ln1g, ln1b);

    for (int l = 0; l < NL; l++) {
        k_gemm_h<<<dim3(2304/128, MT), 256, SMEM_GH>>>(
            h0, h1, q0 + (size_t)l*2304*DM, q1 + (size_t)l*2304*DM,
            qkvb + (size_t)l*2304, nullptr, nullptr, qk0, qk1,
            BT, 2304, DM, DM, INV_W, 3);
        k_scores_h<<<dim3(5, 5, NIMG*NHD), 256, SMEM_SC>>>();
        k_combine <<<NCMB, 256>>>();
        k_av_h    <<<dim3(5, NIMG*NHD), 256, SMEM_AV>>>();
        // proj: split-K 2 -> fused reduce + residual + ln2
        k_gemm_h<<<dim3(DM/128, MT, 2), 256, SMEM_GH>>>(
            a0, a1, pr0 + (size_t)l*DM*DM, pr1 + (size_t)l*DM*DM,
            nullptr, nullptr, ppart, nullptr, nullptr,
            BT, DM, 384, 768, INV_W, 4);
        k_redln<<<BT, 256>>>(ppart, 2, INV_W, projb + (size_t)l*DM, px,
                             ln2g + (size_t)l*DM, ln2b + (size_t)l*DM);
        k_gemm_h<<<dim3(3072/128, MT), 256, SMEM_GH>>>(
            h0, h1, f10 + (size_t)l*3072*DM, f11 + (size_t)l*3072*DM,
            fc1b + (size_t)l*3072, nullptr, nullptr, m0, m1,
            BT, 3072, DM, DM, INV_W, 1);
        // fc2: split-K 4 -> fused reduce + residual + next ln1 (or plain last)
        k_gemm_h<<<dim3(DM/128, MT, 4), 256, SMEM_GH>>>(
            m0, m1, f20 + (size_t)l*DM*3072, f21 + (size_t)l*DM*3072,
            nullptr, nullptr, ppart, nullptr, nullptr,
            BT, DM, 768, 3072, INV_W, 4);
        if (l + 1 < NL) {
            k_redln<<<BT, 256>>>(ppart, 4, INV_W, fc2b + (size_t)l*DM, px,
                                 ln1g + (size_t)(l+1)*DM, ln1b + (size_t)(l+1)*DM);
        } else {
            k_red<<<R4, 256>>>(ppart, 4, INV_W, fc2b + (size_t)l*DM, px, px,
                               DM, BT*DM/4);
        }
    }

    k_lncls<<<NIMG, 256>>>(px, ph, normg, normb);
    k_loss<<<1, 256>>>((float*)d_out);
}

// round 17
// speedup vs baseline: 1.1980x; 1.0159x over previous
#include <cuda_runtime.h>
#include <cuda_fp16.h>
#include <math.h>
#include <stdint.h>

// ---------------- problem constants ----------------
#define IH 384
#define IW 384
#define NPIX (IH*IW)
#define NIMG 4
#define NT 577
#define DM 768
#define NL 12
#define NHD 12
#define BT (NIMG*NT)    // 2308
#define NPATCH 576
#define BIGF 1e4f
#define SPF 640

// static scales
#define WS  4096.f
#define AS  256.f
#define PS  32.f
#define SS  256.f

// ---------------- scratch ----------------
__device__ float d_g2fg[NIMG*NPIX];
__device__ float d_g2bg[NIMG*NPIX];
__device__ float d_tok [NIMG*NPATCH*DM];
__device__ float d_x   [BT*DM];
__device__ __align__(128) float d_S[(size_t)NIMG*NHD*NT*SPF];
__device__ float2 d_rs [NIMG*NHD*NT];
__device__ float2 d_ps [(size_t)NIMG*NHD*NT*5];
__device__ float d_part[(size_t)4*BT*DM];

// compact last-layer buffers (4 cls rows)
__device__ float d_xc [4*DM];
__device__ float d_xc2[4*DM];
__device__ float d_xf [4*DM];
__device__ float d_hf [4*DM];
__device__ __align__(128) __half d_ac0[4*DM],   d_ac1[4*DM];
__device__ __align__(128) __half d_hc0[4*DM],   d_hc1[4*DM];
__device__ __align__(128) __half d_mc0[4*3072], d_mc1[4*3072];

__device__ __align__(128) __half d_h0[BT*DM],    d_h1[BT*DM];
__device__ __align__(128) __half d_a0[BT*DM],    d_a1[BT*DM];
__device__ __align__(128) __half d_m0[BT*3072],  d_m1[BT*3072];
__device__ __align__(128) __half d_p0[NIMG*NPATCH*256], d_p1[NIMG*NPATCH*256];
__device__ __align__(128) __half d_q0[BT*3*DM],  d_q1[BT*3*DM];

__device__ __align__(128) __half d_ws0[DM*256],       d_ws1[DM*256];
__device__ __align__(128) __half d_qT0[NL*2304*DM],   d_qT1[NL*2304*DM];
__device__ __align__(128) __half d_pT0[NL*DM*DM],     d_pT1[NL*DM*DM];
__device__ __align__(128) __half d_f1T0[NL*3072*DM],  d_f1T1[NL*3072*DM];
__device__ __align__(128) __half d_f2T0[NL*DM*3072],  d_f2T1[NL*DM*3072];

// ---------------- helpers ----------------
__device__ __forceinline__ void split2h(float x, float s, __half& h0, __half& h1) {
    float xs = x * s;
    h0 = __float2half_rn(xs);
    h1 = __float2half_rn(xs - __half2float(h0));
}
__device__ __forceinline__ uint32_t s2u(const void* p) {
    uint32_t a;
    asm("{ .reg .u64 t; cvta.to.shared.u64 t, %1; cvt.u32.u64 %0, t; }" : "=r"(a) : "l"(p));
    return a;
}
#define CP16(s,g)  asm volatile("cp.async.cg.shared.global [%0], [%1], 16;" :: "r"(s), "l"(g))
#define CPCOMMIT() asm volatile("cp.async.commit_group;")
#define CPWAIT0()  asm volatile("cp.async.wait_group 0;")

__device__ __forceinline__ void ldsm4(unsigned &r0, unsigned &r1, unsigned &r2,
                                      unsigned &r3, uint32_t addr) {
    asm volatile("ldmatrix.sync.aligned.m8n8.x4.shared.b16 {%0,%1,%2,%3}, [%4];"
        : "=r"(r0), "=r"(r1), "=r"(r2), "=r"(r3) : "r"(addr));
}
__device__ __forceinline__ void ldsm4t(unsigned &r0, unsigned &r1, unsigned &r2,
                                       unsigned &r3, uint32_t addr) {
    asm volatile("ldmatrix.sync.aligned.m8n8.x4.trans.shared.b16 {%0,%1,%2,%3}, [%4];"
        : "=r"(r0), "=r"(r1), "=r"(r2), "=r"(r3) : "r"(addr));
}
#define MMA_F16(c, a, b0v, b1v) \
    asm volatile("mma.sync.aligned.m16n8k16.row.col.f32.f16.f16.f32 " \
                 "{%0,%1,%2,%3},{%4,%5,%6,%7},{%8,%9},{%0,%1,%2,%3};" \
                 : "+f"((c)[0]), "+f"((c)[1]), "+f"((c)[2]), "+f"((c)[3]) \
                 : "r"((a)[0]), "r"((a)[1]), "r"((a)[2]), "r"((a)[3]), \
                   "r"(b0v), "r"(b1v))

// ---------------- EDT row pass (mask fused) ----------------
__global__ void k_edt_row(const float* __restrict__ logits, const int* __restrict__ tr) {
    int idx = blockIdx.x*blockDim.x + threadIdx.x;
    if (idx >= NIMG*IH) return;
    int img = idx / IH, i = idx % IH;
    float* gf = d_g2fg + (size_t)img*NPIX + (size_t)i*IW;
    float* gb = d_g2bg + (size_t)img*NPIX + (size_t)i*IW;
    const float* l0p = logits + ((size_t)img*2)*NPIX + (size_t)i*IW;
    const float* l1p = l0p + NPIX;
    const int*   trp = tr + (size_t)(img-2)*NPIX + (size_t)i*IW;
    bool islog = (img < 2);

    float lf = -BIGF, lb = -BIGF;
    for (int j = 0; j < IW; j++) {
        bool mz = islog ? !(l1p[j] > l0p[j]) : (trp[j] == 0);
        float jj = (float)j;
        if (mz) lf = jj; else lb = jj;
        gf[j] = jj - lf;
        gb[j] = jj - lb;
    }
    float rf = BIGF, rb = BIGF;
    for (int j = IW-1; j >= 0; j--) {
        bool mz = islog ? !(l1p[j] > l0p[j]) : (trp[j] == 0);
        float jj = (float)j;
        if (mz) rf = jj; else rb = jj;
        float g1 = fminf(fminf(gf[j], rf - jj), BIGF);
        float g2 = fminf(fminf(gb[j], rb - jj), BIGF);
        gf[j] = g1*g1;
        gb[j] = g2*g2;
    }
}

// ---------------- EDT column pass + SDM + patch-split write ----------------
__global__ void k_edt_col() {
    int idx = blockIdx.x*blockDim.x + threadIdx.x;
    if (idx >= NIMG*NPIX) return;
    int img = idx / NPIX, r = idx % NPIX;
    int i = r / IW, j = r % IW;
    const float* gf = d_g2fg + (size_t)img*NPIX;
    const float* gb = d_g2bg + (size_t)img*NPIX;
    float mf = 3.4e38f, mb = 3.4e38f;
    float fi = (float)i;
    for (int ii = 0; ii < IH; ii++) {
        float off = fi - (float)ii; off *= off;
        mf = fminf(mf, gf[(size_t)ii*IW + j] + off);
        mb = fminf(mb, gb[(size_t)ii*IW + j] + off);
    }
    float v = sqrtf(mb) - sqrtf(mf);
    int t = (i >> 4)*24 + (j >> 4);
    int k = ((i & 15) << 4) + (j & 15);
    size_t o = (size_t)img*NPATCH*256 + (size_t)t*256 + k;
    split2h(v, PS, d_p0[o], d_p1[o]);
}

// ---------------- weight prep ----------------
__global__ void k_wsumT(const float* __restrict__ pw) {
    int idx = blockIdx.x*blockDim.x + threadIdx.x;
    if (idx >= DM*256) return;
    int o = idx / 256, k = idx % 256;
    float v = pw[(size_t)k*DM + o] + pw[(size_t)(256+k)*DM + o] + pw[(size_t)(512+k)*DM + o];
    split2h(v, WS, d_ws0[idx], d_ws1[idx]);
}

__global__ void k_tsplit(const float* __restrict__ W, __half* __restrict__ T0,
                         __half* __restrict__ T1, int K, int N) {
    __shared__ float t[32][33];
    size_t off = (size_t)blockIdx.z * K * N;
    const float* w = W + off;
    int bx = blockIdx.x*32, by = blockIdx.y*32;
    int tx = threadIdx.x, ty = threadIdx.y;
    #pragma unroll
    for (int r = 0; r < 4; r++)
        t[ty + r*8][tx] = w[(size_t)(by + ty + r*8)*N + bx + tx];
    __syncthreads();
    #pragma unroll
    for (int r = 0; r < 4; r++) {
        int n = bx + ty + r*8, k = by + tx;
        float v = t[tx][ty + r*8];
        size_t o = off + (size_t)n*K + k;
        split2h(v, WS, T0[o], T1[o]);
    }
}

__global__ void k_assemble(const float* __restrict__ cls, const float* __restrict__ pos) {
    int idx = blockIdx.x*blockDim.x + threadIdx.x;
    if (idx >= BT*DM) return;
    int img = idx / (NT*DM);
    int rem = idx % (NT*DM);
    int t = rem / DM, c = rem % DM;
    float v = (t == 0) ? cls[c] : d_tok[((size_t)img*NPATCH + (t-1))*DM + c];
    d_x[idx] = v + pos[(size_t)t*DM + c];
}

// ---------------- layernorm (generic: in fp32, out split planes) -----------
__global__ void k_ln(const float* __restrict__ in, __half* __restrict__ o0,
                     __half* __restrict__ o1,
                     const float* __restrict__ g, const float* __restrict__ b) {
    int row = blockIdx.x;
    int tid = threadIdx.x;
    const float* xr = in + (size_t)row*DM;
    __shared__ float red[256];
    float v[3];
    #pragma unroll
    for (int i = 0; i < 3; i++) v[i] = xr[tid + i*256];
    float s = v[0] + v[1] + v[2];
    red[tid] = s; __syncthreads();
    for (int o = 128; o > 0; o >>= 1) { if (tid < o) red[tid] += red[tid+o]; __syncthreads(); }
    float mu = red[0] * (1.f/768.f);
    __syncthreads();
    float var = 0.f;
    #pragma unroll
    for (int i = 0; i < 3; i++) { float dd = v[i]-mu; var += dd*dd; }
    red[tid] = var; __syncthreads();
    for (int o = 128; o > 0; o >>= 1) { if (tid < o) red[tid] += red[tid+o]; __syncthreads(); }
    float rstd = rsqrtf(red[0] * (1.f/768.f) + 1e-6f);
    #pragma unroll
    for (int i = 0; i < 3; i++) {
        int c = tid + i*256;
        float val = (v[i]-mu)*rstd*g[c] + b[c];
        size_t o = (size_t)row*DM + c;
        split2h(val, AS, o0[o], o1[o]);
    }
}

// ---------------- fused split-K reduce + residual + LN + split write --------
__global__ void k_redln(const float* __restrict__ P, int ns, float inv,
                        const float* __restrict__ bias, float* __restrict__ x,
                        const float* __restrict__ g, const float* __restrict__ b) {
    int row = blockIdx.x;
    int tid = threadIdx.x;
    __shared__ float red[256];
    const size_t MN = (size_t)BT*DM;
    float v[3];
    #pragma unroll
    for (int i = 0; i < 3; i++) {
        int c = tid + i*256;
        size_t o = (size_t)row*DM + c;
        float s = P[o];
        for (int z = 1; z < ns; z++) s += P[(size_t)z*MN + o];
        v[i] = s*inv + bias[c] + x[o];
        x[o] = v[i];
    }
    float s = v[0] + v[1] + v[2];
    red[tid] = s; __syncthreads();
    for (int o = 128; o > 0; o >>= 1) { if (tid < o) red[tid] += red[tid+o]; __syncthreads(); }
    float mu = red[0] * (1.f/768.f);
    __syncthreads();
    float var = 0.f;
    #pragma unroll
    for (int i = 0; i < 3; i++) { float dd = v[i]-mu; var += dd*dd; }
    red[tid] = var; __syncthreads();
    for (int o = 128; o > 0; o >>= 1) { if (tid < o) red[tid] += red[tid+o]; __syncthreads(); }
    float rstd = rsqrtf(red[0] * (1.f/768.f) + 1e-6f);
    #pragma unroll
    for (int i = 0; i < 3; i++) {
        int c = tid + i*256;
        float val = (v[i]-mu)*rstd*g[c] + b[c];
        size_t o = (size_t)row*DM + c;
        split2h(val, AS, d_h0[o], d_h1[o]);
    }
}

// ---------------- LN (fp32 in -> fp32 out), compact rows ----------------
__global__ void k_lnf(const float* __restrict__ in, float* __restrict__ out,
                      const float* __restrict__ g, const float* __restrict__ b) {
    int row = blockIdx.x;
    int tid = threadIdx.x;
    const float* xr = in + (size_t)row*DM;
    __shared__ float red[256];
    float v[3];
    #pragma unroll
    for (int i = 0; i < 3; i++) v[i] = xr[tid + i*256];
    float s = v[0] + v[1] + v[2];
    red[tid] = s; __syncthreads();
    for (int o = 128; o > 0; o >>= 1) { if (tid < o) red[tid] += red[tid+o]; __syncthreads(); }
    float mu = red[0] * (1.f/768.f);
    __syncthreads();
    float var = 0.f;
    #pragma unroll
    for (int i = 0; i < 3; i++) { float dd = v[i]-mu; var += dd*dd; }
    red[tid] = var; __syncthreads();
    for (int o = 128; o > 0; o >>= 1) { if (tid < o) red[tid] += red[tid+o]; __syncthreads(); }
    float rstd = rsqrtf(red[0] * (1.f/768.f) + 1e-6f);
    #pragma unroll
    for (int i = 0; i < 3; i++) {
        int c = tid + i*256;
        out[(size_t)row*DM + c] = (v[i]-mu)*rstd*g[c] + b[c];
    }
}

// ---------------- gather 4 cls rows (attention out + residual) -------------
__global__ void k_gather4() {
    int b = blockIdx.x, tid = threadIdx.x;
    size_t src = (size_t)b*NT*DM;
    #pragma unroll
    for (int i = 0; i < 3; i++) {
        int c = tid + i*256;
        d_ac0[b*DM + c] = d_a0[src + c];
        d_ac1[b*DM + c] = d_a1[src + c];
        d_xc [b*DM + c] = d_x [src + c];
    }
}

// ---------------- shared epilogue ----------------
__device__ __forceinline__ void gemm_epilogue(
        float v0, float v1, int gr, int gc, int N, int epi,
        const float* res, float* C, __half* C0, __half* C1) {
    if (epi == 1 || epi == 3) {
        if (epi == 1) {
            v0 = 0.5f*v0*(1.f + erff(v0*0.70710678118654752f));
            v1 = 0.5f*v1*(1.f + erff(v1*0.70710678118654752f));
        }
        size_t o = (size_t)gr*N + gc;
        __half h00, h01, h10, h11;
        split2h(v0, AS, h00, h01);
        split2h(v1, AS, h10, h11);
        __half2 p0; p0.x = h00; p0.y = h10;
        __half2 p1; p1.x = h01; p1.y = h11;
        *(__half2*)&C0[o] = p0;
        *(__half2*)&C1[o] = p1;
    } else {
        if (epi == 2) {
            float2 r2 = *(const float2*)&res[(size_t)gr*N + gc];
            v0 += r2.x; v1 += r2.y;
        }
        *(float2*)&C[(size_t)gr*N + gc] = make_float2(v0, v1);
    }
}

// ================= GEMM A: 256 threads, 128x128 tile, optional split-K ======
#define APL 10240u
#define BPL128 10240u
#define BUFB128 (2u*APL + 2u*BPL128)
#define SMEM_GH (2u*BUFB128)

__global__ __launch_bounds__(256, 2) void k_gemm_h(
        const __half* __restrict__ A0, const __half* __restrict__ A1,
        const __half* __restrict__ B0, const __half* __restrict__ B1,
        const float* __restrict__ bias, const float* __restrict__ res,
        float* __restrict__ C, __half* __restrict__ C0, __half* __restrict__ C1,
        int M, int N, int K, int LDK, float inv, int epi) {
    extern __shared__ char smem[];
    uint32_t sb = s2u(smem);
    int tid = threadIdx.x, lane = tid & 31, warp = tid >> 5;
    int wm = (warp & 3)*32, wn = (warp >> 2)*64;
    int bm = blockIdx.y*128, bn = blockIdx.x*128;
    size_t koff = (size_t)blockIdx.z * K;
    int g = lane >> 2, q = lane & 3;

    float acc[2][8][4];
    #pragma unroll
    for (int i=0;i<2;i++)
        #pragma unroll
        for (int j=0;j<8;j++)
            #pragma unroll
            for (int r=0;r<4;r++) acc[i][j][r]=0.f;

    int lrow = tid >> 2;
    int lc   = tid & 3;

    auto load_chunk = [&](int kt, int buf) {
        int k0 = kt * 32;
        uint32_t base = sb + (uint32_t)buf * BUFB128;
        const __half* Ap[2] = {A0, A1};
        const __half* Bp[2] = {B0, B1};
        #pragma unroll
        for (int p = 0; p < 2; p++) {
            #pragma unroll
            for (int l = 0; l < 2; l++) {
                int row = lrow + l*64;
                int gr = bm + row; if (gr >= M) gr = M - 1;
                CP16(base + p*APL + (uint32_t)(row*80 + lc*16),
                     Ap[p] + (size_t)gr*LDK + koff + k0 + lc*8);
                CP16(base + 2*APL + p*BPL128 + (uint32_t)(row*80 + lc*16),
                     Bp[p] + (size_t)(bn + row)*LDK + koff + k0 + lc*8);
            }
        }
    };

    int KT = K >> 5;
    load_chunk(0, 0);
    CPCOMMIT();
    for (int kt = 0; kt < KT; kt++) {
        CPWAIT0();
        __syncthreads();
        if (kt + 1 < KT) { load_chunk(kt + 1, (kt + 1) & 1); CPCOMMIT(); }
        uint32_t base = sb + (uint32_t)(kt & 1) * BUFB128;
        uint32_t aBase = base + (uint32_t)((wm + (lane & 15))*80 + (lane >> 4)*16);
        int bn8 = (lane & 7) + ((lane >> 4) << 3);
        uint32_t bBase = base + 2*APL + (uint32_t)((wn + bn8)*80 + ((lane >> 3) & 1)*16);
        #pragma unroll
        for (int ks = 0; ks < 2; ks++) {
            unsigned a0f[2][4], a1f[2][4];
            #pragma unroll
            for (int mi = 0; mi < 2; mi++) {
                ldsm4(a0f[mi][0],a0f[mi][1],a0f[mi][2],a0f[mi][3],
                      aBase + mi*1280u + ks*32u);
                ldsm4(a1f[mi][0],a1f[mi][1],a1f[mi][2],a1f[mi][3],
                      aBase + APL + mi*1280u + ks*32u);
            }
            #pragma unroll
            for (int nq = 0; nq < 4; nq++) {
                unsigned b0f[4], b1f[4];
                ldsm4(b0f[0],b0f[1],b0f[2],b0f[3], bBase + nq*1280u + ks*32u);
                ldsm4(b1f[0],b1f[1],b1f[2],b1f[3], bBase + BPL128 + nq*1280u + ks*32u);
                #pragma unroll
                for (int mi = 0; mi < 2; mi++)
                    #pragma unroll
                    for (int h = 0; h < 2; h++) {
                        MMA_F16(acc[mi][nq*2+h], a0f[mi], b0f[h*2], b0f[h*2+1]);
                        MMA_F16(acc[mi][nq*2+h], a0f[mi], b1f[h*2], b1f[h*2+1]);
                        MMA_F16(acc[mi][nq*2+h], a1f[mi], b0f[h*2], b0f[h*2+1]);
                    }
            }
        }
    }
    __syncthreads();

    size_t pofs = (size_t)blockIdx.z * M * N;
    #pragma unroll
    for (int mi = 0; mi < 2; mi++)
        #pragma unroll
        for (int rr = 0; rr < 2; rr++) {
            int gr = bm + wm + mi*16 + g + rr*8;
            if (gr >= M) continue;
            #pragma unroll
            for (int nj = 0; nj < 8; nj++) {
                int gc = bn + wn + nj*8 + 2*q;
                if (epi == 4) {
                    *(float2*)&C[pofs + (size_t)gr*N + gc] =
                        make_float2(acc[mi][nj][rr*2+0], acc[mi][nj][rr*2+1]);
                } else {
                    gemm_epilogue(acc[mi][nj][rr*2+0]*inv + bias[gc],
                                  acc[mi][nj][rr*2+1]*inv + bias[gc+1],
                                  gr, gc, N, epi, res, C, C0, C1);
                }
            }
        }
}

// ================= GEMM W: 512 threads, 128x128 tile (patch) ===============
__global__ __launch_bounds__(512, 1) void k_gemm_w(
        const __half* __restrict__ A0, const __half* __restrict__ A1,
        const __half* __restrict__ B0, const __half* __restrict__ B1,
        const float* __restrict__ bias, const float* __restrict__ res,
        float* __restrict__ C, __half* __restrict__ C0, __half* __restrict__ C1,
        int M, int N, int K, float inv, int epi) {
    extern __shared__ char smem[];
    uint32_t sb = s2u(smem);
    int tid = threadIdx.x, lane = tid & 31, warp = tid >> 5;
    int wm = (warp & 3)*32, wn = (warp >> 2)*32;
    int bm = blockIdx.y*128, bn = blockIdx.x*128;
    int g = lane >> 2, q = lane & 3;

    float acc[2][4][4];
    #pragma unroll
    for (int i=0;i<2;i++)
        #pragma unroll
        for (int j=0;j<4;j++)
            #pragma unroll
            for (int r=0;r<4;r++) acc[i][j][r]=0.f;

    int lrow = tid >> 2;
    int lc   = tid & 3;

    auto load_chunk = [&](int kt, int buf) {
        int k0 = kt * 32;
        uint32_t base = sb + (uint32_t)buf * BUFB128;
        const __half* Ap[2] = {A0, A1};
        const __half* Bp[2] = {B0, B1};
        int gr = bm + lrow; if (gr >= M) gr = M - 1;
        #pragma unroll
        for (int p = 0; p < 2; p++) {
            CP16(base + p*APL + (uint32_t)(lrow*80 + lc*16),
                 Ap[p] + (size_t)gr*K + k0 + lc*8);
            CP16(base + 2*APL + p*BPL128 + (uint32_t)(lrow*80 + lc*16),
                 Bp[p] + (size_t)(bn + lrow)*K + k0 + lc*8);
        }
    };

    int KT = K >> 5;
    load_chunk(0, 0);
    CPCOMMIT();
    for (int kt = 0; kt < KT; kt++) {
        CPWAIT0();
        __syncthreads();
        if (kt + 1 < KT) { load_chunk(kt + 1, (kt + 1) & 1); CPCOMMIT(); }
        uint32_t base = sb + (uint32_t)(kt & 1) * BUFB128;
        uint32_t aBase = base + (uint32_t)((wm + (lane & 15))*80 + (lane >> 4)*16);
        int bn8 = (lane & 7) + ((lane >> 4) << 3);
        uint32_t bBase = base + 2*APL + (uint32_t)((wn + bn8)*80 + ((lane >> 3) & 1)*16);
        #pragma unroll
        for (int ks = 0; ks < 2; ks++) {
            unsigned a0f[2][4], a1f[2][4];
            #pragma unroll
            for (int mi = 0; mi < 2; mi++) {
                ldsm4(a0f[mi][0],a0f[mi][1],a0f[mi][2],a0f[mi][3],
                      aBase + mi*1280u + ks*32u);
                ldsm4(a1f[mi][0],a1f[mi][1],a1f[mi][2],a1f[mi][3],
                      aBase + APL + mi*1280u + ks*32u);
            }
            #pragma unroll
            for (int nq = 0; nq < 2; nq++) {
                unsigned b0f[4], b1f[4];
                ldsm4(b0f[0],b0f[1],b0f[2],b0f[3], bBase + nq*1280u + ks*32u);
                ldsm4(b1f[0],b1f[1],b1f[2],b1f[3], bBase + BPL128 + nq*1280u + ks*32u);
                #pragma unroll
                for (int mi = 0; mi < 2; mi++)
                    #pragma unroll
                    for (int h = 0; h < 2; h++) {
                        MMA_F16(acc[mi][nq*2+h], a0f[mi], b0f[h*2], b0f[h*2+1]);
                        MMA_F16(acc[mi][nq*2+h], a0f[mi], b1f[h*2], b1f[h*2+1]);
                        MMA_F16(acc[mi][nq*2+h], a1f[mi], b0f[h*2], b0f[h*2+1]);
                    }
            }
        }
    }
    __syncthreads();

    #pragma unroll
    for (int mi = 0; mi < 2; mi++)
        #pragma unroll
        for (int rr = 0; rr < 2; rr++) {
            int gr = bm + wm + mi*16 + g + rr*8;
            if (gr >= M) continue;
            #pragma unroll
            for (int nj = 0; nj < 4; nj++) {
                int gc = bn + wn + nj*8 + 2*q;
                gemm_epilogue(acc[mi][nj][rr*2+0]*inv + bias[gc],
                              acc[mi][nj][rr*2+1]*inv + bias[gc+1],
                              gr, gc, N, epi, res, C, C0, C1);
            }
        }
}

// ================= attention scores + per-tile softmax stats =================
#define SROW 144u
#define SPL  (128u*SROW)
#define SMEM_SC (4u*SPL)

__global__ __launch_bounds__(256, 2) void k_scores_h() {
    extern __shared__ char smem[];
    uint32_t sb = s2u(smem);
    int bh = blockIdx.z, b = bh / NHD, h = bh % NHD;
    int m0 = blockIdx.y*128, n0 = blockIdx.x*128;
    int tid = threadIdx.x, lane = tid & 31, warp = tid >> 5;
    int wm = (warp & 3)*32, wn = (warp >> 2)*64;
    int g = lane >> 2, q = lane & 3;

    #pragma unroll
    for (int l = 0; l < 4; l++) {
        int id = tid + l*256;
        int row = id >> 3, c = id & 7;
        int gm = m0 + row; if (gm >= NT) gm = NT - 1;
        int gn = n0 + row; if (gn >= NT) gn = NT - 1;
        size_t qo = (size_t)(b*NT + gm)*2304 + h*64 + c*8;
        size_t ko = (size_t)(b*NT + gn)*2304 + 768 + h*64 + c*8;
        uint32_t so = (uint32_t)(row*SROW + c*16);
        CP16(sb + so,          d_q0 + qo);
        CP16(sb + SPL + so,    d_q1 + qo);
        CP16(sb + 2*SPL + so,  d_q0 + ko);
        CP16(sb + 3*SPL + so,  d_q1 + ko);
    }
    CPCOMMIT(); CPWAIT0();
    __syncthreads();

    float acc[2][8][4];
    #pragma unroll
    for (int i=0;i<2;i++)
        #pragma unroll
        for (int j=0;j<8;j++)
            #pragma unroll
            for (int r=0;r<4;r++) acc[i][j][r]=0.f;

    uint32_t aBase = sb + (uint32_t)((wm + (lane & 15))*SROW + (lane >> 4)*16);
    int bn8 = (lane & 7) + ((lane >> 4) << 3);
    uint32_t bBase = sb + 2*SPL + (uint32_t)((wn + bn8)*SROW + ((lane >> 3) & 1)*16);

    #pragma unroll
    for (int ks = 0; ks < 4; ks++) {
        unsigned a0f[2][4], a1f[2][4];
        #pragma unroll
        for (int mi = 0; mi < 2; mi++) {
            ldsm4(a0f[mi][0],a0f[mi][1],a0f[mi][2],a0f[mi][3],
                  aBase + mi*16*SROW + ks*32u);
            ldsm4(a1f[mi][0],a1f[mi][1],a1f[mi][2],a1f[mi][3],
                  aBase + SPL + mi*16*SROW + ks*32u);
        }
        #pragma unroll
        for (int nq = 0; nq < 4; nq++) {
            unsigned b0f[4], b1f[4];
            ldsm4(b0f[0],b0f[1],b0f[2],b0f[3], bBase + nq*16*SROW + ks*32u);
            ldsm4(b1f[0],b1f[1],b1f[2],b1f[3], bBase + SPL + nq*16*SROW + ks*32u);
            #pragma unroll
            for (int mi = 0; mi < 2; mi++)
                #pragma unroll
                for (int hh = 0; hh < 2; hh++) {
                    MMA_F16(acc[mi][nq*2+hh], a0f[mi], b0f[hh*2], b0f[hh*2+1]);
                    MMA_F16(acc[mi][nq*2+hh], a0f[mi], b1f[hh*2], b1f[hh*2+1]);
                    MMA_F16(acc[mi][nq*2+hh], a1f[mi], b0f[hh*2], b0f[hh*2+1]);
                }
        }
    }

    const float SCL = 0.125f/(AS*AS);
    float* sbase = d_S + (size_t)bh*NT*SPF;
    #pragma unroll
    for (int mi = 0; mi < 2; mi++)
        #pragma unroll
        for (int rr = 0; rr < 2; rr++) {
            int gm = m0 + wm + mi*16 + g + rr*8;
            if (gm >= NT) continue;
            #pragma unroll
            for (int nj = 0; nj < 8; nj++) {
                int gc = n0 + wn + nj*8 + 2*q;
                if (gc < NT)   sbase[(size_t)gm*SPF + gc]   = acc[mi][nj][rr*2+0]*SCL;
                if (gc+1 < NT) sbase[(size_t)gm*SPF + gc+1] = acc[mi][nj][rr*2+1]*SCL;
            }
        }

    // ---- per-tile softmax stats ----
    __syncthreads();
    float2* shst = (float2*)smem;
    #pragma unroll
    for (int mi = 0; mi < 2; mi++)
        #pragma unroll
        for (int rr = 0; rr < 2; rr++) {
            int rl = wm + mi*16 + g + rr*8;
            float vv[16];
            float mx = -3.4e38f;
            #pragma unroll
            for (int nj = 0; nj < 8; nj++) {
                int gc = n0 + wn + nj*8 + 2*q;
                float v0 = (gc   < NT) ? acc[mi][nj][rr*2+0]*SCL : -3.4e38f;
                float v1 = (gc+1 < NT) ? acc[mi][nj][rr*2+1]*SCL : -3.4e38f;
                vv[nj*2]   = v0;
                vv[nj*2+1] = v1;
                mx = fmaxf(mx, fmaxf(v0, v1));
            }
            mx = fmaxf(mx, __shfl_xor_sync(0xffffffffu, mx, 1));
            mx = fmaxf(mx, __shfl_xor_sync(0xffffffffu, mx, 2));
            float sm = 0.f;
            #pragma unroll
            for (int j = 0; j < 16; j++) sm += __expf(vv[j] - mx);
            sm += __shfl_xor_sync(0xffffffffu, sm, 1);
            sm += __shfl_xor_sync(0xffffffffu, sm, 2);
            if (q == 0) shst[(warp >> 2)*128 + rl] = make_float2(mx, sm);
        }
    __syncthreads();
    if (tid < 128) {
        float2 a2 = shst[tid], b2 = shst[128 + tid];
        float M = fmaxf(a2.x, b2.x);
        float S = a2.y*__expf(a2.x - M) + b2.y*__expf(b2.x - M);
        int gm = m0 + tid;
        if (gm < NT)
            d_ps[((size_t)bh*NT + gm)*5 + blockIdx.x] = make_float2(M, S);
    }
}

// ---------------- combine per-tile stats -> row stats ----------------
__global__ void k_combine() {
    int r = blockIdx.x*blockDim.x + threadIdx.x;
    if (r >= NIMG*NHD*NT) return;
    const float2* p = &d_ps[(size_t)r*5];
    float2 p0 = p[0], p1 = p[1], p2 = p[2], p3 = p[3], p4 = p[4];
    float M = fmaxf(fmaxf(fmaxf(p0.x, p1.x), fmaxf(p2.x, p3.x)), p4.x);
    float S = p0.y*__expf(p0.x - M) + p1.y*__expf(p1.x - M)
            + p2.y*__expf(p2.x - M) + p3.y*__expf(p3.x - M)
            + p4.y*__expf(p4.x - M);
    d_rs[r] = make_float2(M, SS / S);
}

// ================= AV: fused exp/normalize + split + MMA ====================
#define AV_RS   0u
#define AV_P0   1024u
#define AV_P1   11264u
#define AV_BUF0 21504u
#define AV_FB   18432u
#define AV_VPL  4608u
#define AV_BUFSZ (AV_FB + 2u*AV_VPL)
#define SMEM_AV (AV_BUF0 + 2u*AV_BUFSZ)

__global__ __launch_bounds__(256, 2) void k_av_h() {
    extern __shared__ char smem[];
    uint32_t sb = s2u(smem);
    int bh = blockIdx.y, b = bh / NHD, h = bh % NHD;
    int m0 = blockIdx.x*128;
    int tid = threadIdx.x, lane = tid & 31, warp = tid >> 5;
    int wm = (warp & 3)*32, wn = (warp >> 2)*32;
    int g = lane >> 2, q = lane & 3;

    float acc[2][4][4];
    #pragma unroll
    for (int i=0;i<2;i++)
        #pragma unroll
        for (int j=0;j<4;j++)
            #pragma unroll
            for (int r=0;r<4;r++) acc[i][j][r]=0.f;

    const float* Sf = d_S + (size_t)bh*NT*SPF;

    if (tid < 128) {
        int gm = m0 + tid; if (gm >= NT) gm = NT - 1;
        *(float2*)(smem + AV_RS + tid*8) = d_rs[(size_t)bh*NT + gm];
    }

    auto load_chunk = [&](int kt, int buf) {
        int k0 = kt * 32;
        uint32_t base = sb + AV_BUF0 + (uint32_t)buf * AV_BUFSZ;
        #pragma unroll
        for (int l = 0; l < 4; l++) {
            int id = tid + l*256;
            int row = id >> 3, c = id & 7;
            int gm = m0 + row; if (gm >= NT) gm = NT - 1;
            CP16(base + (uint32_t)(row*144 + c*16),
                 Sf + (size_t)gm*SPF + k0 + c*4);
        }
        {
            int row = tid >> 3, c = tid & 7;
            int gk = k0 + row; if (gk >= NT) gk = NT - 1;
            size_t vo = (size_t)(b*NT + gk)*2304 + 1536 + h*64 + c*8;
            uint32_t d = (uint32_t)(row*144 + c*16);
            CP16(base + AV_FB + d,           d_q0 + vo);
            CP16(base + AV_FB + AV_VPL + d,  d_q1 + vo);
        }
    };

    const int KT = (NT + 31) / 32;   // 19
    load_chunk(0, 0);
    CPCOMMIT();
    for (int kt = 0; kt < KT; kt++) {
        int buf = kt & 1;
        int k0 = kt * 32;
        CPWAIT0();
        __syncthreads();
        if (kt + 1 < KT) { load_chunk(kt + 1, (kt + 1) & 1); CPCOMMIT(); }
        {
            int row = tid >> 1, colh = (tid & 1)*16;
            float2 ri = *(const float2*)(smem + AV_RS + row*8);
            const float* F = (const float*)(smem + AV_BUF0 + buf*AV_BUFSZ) + row*36 + colh;
            char* P0w = smem + AV_P0 + row*80 + colh*2;
            char* P1w = smem + AV_P1 + row*80 + colh*2;
            #pragma unroll
            for (int j = 0; j < 16; j += 2) {
                int k = k0 + colh + j;
                float f0 = F[j], f1 = F[j+1];
                float p0 = (k     < NT) ? __expf(f0 - ri.x)*ri.y : 0.f;
                float p1 = (k + 1 < NT) ? __expf(f1 - ri.x)*ri.y : 0.f;
                __half a0h = __float2half_rn(p0);
                __half b0h = __float2half_rn(p1);
                __half a1h = __float2half_rn(p0 - __half2float(a0h));
                __half b1h = __float2half_rn(p1 - __half2float(b0h));
                __half2 w0; w0.x = a0h; w0.y = b0h;
                __half2 w1; w1.x = a1h; w1.y = b1h;
                *(__half2*)(P0w + j*2) = w0;
                *(__half2*)(P1w + j*2) = w1;
            }
        }
        __syncthreads();
        uint32_t aBase = sb + AV_P0 + (uint32_t)((wm + (lane & 15))*80 + (lane >> 4)*16);
        uint32_t vb0 = sb + AV_BUF0 + (uint32_t)buf*AV_BUFSZ + AV_FB;
        uint32_t bBase = vb0 + (uint32_t)((lane & 15)*144 + wn*2 + (lane >> 4)*16);
        #pragma unroll
        for (int ks = 0; ks < 2; ks++) {
            unsigned a0f[2][4], a1f[2][4];
            #pragma unroll
            for (int mi = 0; mi < 2; mi++) {
                ldsm4(a0f[mi][0],a0f[mi][1],a0f[mi][2],a0f[mi][3],
                      aBase + mi*16*80u + ks*32u);
                ldsm4(a1f[mi][0],a1f[mi][1],a1f[mi][2],a1f[mi][3],
                      aBase + (AV_P1 - AV_P0) + mi*16*80u + ks*32u);
            }
            #pragma unroll
            for (int nq = 0; nq < 2; nq++) {
                unsigned b0f[4], b1f[4];
                uint32_t ba = bBase + ks*16*144u + nq*32u;
                ldsm4t(b0f[0],b0f[1],b0f[2],b0f[3], ba);
                ldsm4t(b1f[0],b1f[1],b1f[2],b1f[3], ba + AV_VPL);
                #pragma unroll
                for (int mi = 0; mi < 2; mi++)
                    #pragma unroll
                    for (int hh = 0; hh < 2; hh++) {
                        MMA_F16(acc[mi][nq*2+hh], a0f[mi], b0f[hh*2], b0f[hh*2+1]);
                        MMA_F16(acc[mi][nq*2+hh], a0f[mi], b1f[hh*2], b1f[hh*2+1]);
                        MMA_F16(acc[mi][nq*2+hh], a1f[mi], b0f[hh*2], b0f[hh*2+1]);
                    }
            }
        }
    }

    const float INV_AV = 1.f/(SS*AS);
    #pragma unroll
    for (int mi = 0; mi < 2; mi++)
        #pragma unroll
        for (int rr = 0; rr < 2; rr++) {
            int gm = m0 + wm + mi*16 + g + rr*8;
            if (gm >= NT) continue;
            #pragma unroll
            for (int nj = 0; nj < 4; nj++) {
                int gc = wn + nj*8 + 2*q;
                size_t o = (size_t)(b*NT + gm)*DM + h*64 + gc;
                float v0 = acc[mi][nj][rr*2+0]*INV_AV;
                float v1 = acc[mi][nj][rr*2+1]*INV_AV;
                __half h00, h01, h10, h11;
                split2h(v0, AS, h00, h01);
                split2h(v1, AS, h10, h11);
                __half2 p0; p0.x = h00; p0.y = h10;
                __half2 p1; p1.x = h01; p1.y = h11;
                *(__half2*)&d_a0[o] = p0;
                *(__half2*)&d_a1[o] = p1;
            }
        }
}

// ---------------- split-K reduce + residual + LN (as before) ----------------
// (k_redln defined above)

// ---------------- final cosine loss (compact 4x768 input) ----------------
__global__ void k_loss(float* out) {
    __shared__ float sd[256], sa[256], sb2[256];
    int tid = threadIdx.x;
    float coss[2];
    for (int b = 0; b < 2; b++) {
        const float* fp = d_hf + (size_t)b*DM;
        const float* ft = d_hf + (size_t)(2+b)*DM;
        float dt = 0.f, na = 0.f, nb = 0.f;
        for (int c = tid; c < DM; c += 256) {
            float a = fp[c], bb = ft[c];
            dt += a*bb; na += a*a; nb += bb*bb;
        }
        sd[tid] = dt; sa[tid] = na; sb2[tid] = nb; __syncthreads();
        for (int o = 128; o > 0; o >>= 1) {
            if (tid < o) { sd[tid]+=sd[tid+o]; sa[tid]+=sa[tid+o]; sb2[tid]+=sb2[tid+o]; }
            __syncthreads();
        }
        coss[b] = sd[0] / (fmaxf(sqrtf(sa[0]), 1e-8f) * fmaxf(sqrtf(sb2[0]), 1e-8f));
        __syncthreads();
    }
    if (tid == 0) out[0] = 1.f - 0.5f*(coss[0] + coss[1]);
}

// ---------------- launch ----------------
extern "C" void kernel_launch(void* const* d_in, const int* in_sizes, int n_in,
                              void* d_out, int out_size) {
    const float* pred   = (const float*)d_in[0];
    const int*   tru    = (const int*)  d_in[1];
    const float* patchw = (const float*)d_in[2];
    const float* patchb = (const float*)d_in[3];
    const float* cls    = (const float*)d_in[4];
    const float* pos    = (const float*)d_in[5];
    const float* ln1g   = (const float*)d_in[6];
    const float* ln1b   = (const float*)d_in[7];
    const float* qkvw   = (const float*)d_in[8];
    const float* qkvb   = (const float*)d_in[9];
    const float* projw  = (const float*)d_in[10];
    const float* projb  = (const float*)d_in[11];
    const float* ln2g   = (const float*)d_in[12];
    const float* ln2b   = (const float*)d_in[13];
    const float* fc1w   = (const float*)d_in[14];
    const float* fc1b   = (const float*)d_in[15];
    const float* fc2w   = (const float*)d_in[16];
    const float* fc2b   = (const float*)d_in[17];
    const float* normg  = (const float*)d_in[18];
    const float* normb  = (const float*)d_in[19];

    float *px, *ptok, *ppart, *pxc, *pxc2, *pxf, *phf;
    cudaGetSymbolAddress((void**)&px,    d_x);
    cudaGetSymbolAddress((void**)&ptok,  d_tok);
    cudaGetSymbolAddress((void**)&ppart, d_part);
    cudaGetSymbolAddress((void**)&pxc,   d_xc);
    cudaGetSymbolAddress((void**)&pxc2,  d_xc2);
    cudaGetSymbolAddress((void**)&pxf,   d_xf);
    cudaGetSymbolAddress((void**)&phf,   d_hf);

    __half *h0,*h1,*a0,*a1,*m0,*m1,*p0,*p1,*qk0,*qk1;
    __half *ac0,*ac1,*hc0,*hc1,*mc0,*mc1;
    __half *ws0,*ws1,*q0,*q1,*pr0,*pr1,*f10,*f11,*f20,*f21;
    cudaGetSymbolAddress((void**)&h0, d_h0);   cudaGetSymbolAddress((void**)&h1, d_h1);
    cudaGetSymbolAddress((void**)&a0, d_a0);   cudaGetSymbolAddress((void**)&a1, d_a1);
    cudaGetSymbolAddress((void**)&m0, d_m0);   cudaGetSymbolAddress((void**)&m1, d_m1);
    cudaGetSymbolAddress((void**)&p0, d_p0);   cudaGetSymbolAddress((void**)&p1, d_p1);
    cudaGetSymbolAddress((void**)&qk0, d_q0);  cudaGetSymbolAddress((void**)&qk1, d_q1);
    cudaGetSymbolAddress((void**)&ac0, d_ac0); cudaGetSymbolAddress((void**)&ac1, d_ac1);
    cudaGetSymbolAddress((void**)&hc0, d_hc0); cudaGetSymbolAddress((void**)&hc1, d_hc1);
    cudaGetSymbolAddress((void**)&mc0, d_mc0); cudaGetSymbolAddress((void**)&mc1, d_mc1);
    cudaGetSymbolAddress((void**)&ws0, d_ws0); cudaGetSymbolAddress((void**)&ws1, d_ws1);
    cudaGetSymbolAddress((void**)&q0, d_qT0);  cudaGetSymbolAddress((void**)&q1, d_qT1);
    cudaGetSymbolAddress((void**)&pr0, d_pT0); cudaGetSymbolAddress((void**)&pr1, d_pT1);
    cudaGetSymbolAddress((void**)&f10, d_f1T0); cudaGetSymbolAddress((void**)&f11, d_f1T1);
    cudaGetSymbolAddress((void**)&f20, d_f2T0); cudaGetSymbolAddress((void**)&f21, d_f2T1);

    cudaFuncSetAttribute(k_gemm_h, cudaFuncAttributeMaxDynamicSharedMemorySize, SMEM_GH);
    cudaFuncSetAttribute(k_gemm_w, cudaFuncAttributeMaxDynamicSharedMemorySize, SMEM_GH);
    cudaFuncSetAttribute(k_scores_h, cudaFuncAttributeMaxDynamicSharedMemorySize, SMEM_SC);
    cudaFuncSetAttribute(k_av_h,     cudaFuncAttributeMaxDynamicSharedMemorySize, SMEM_AV);

    const float INV_W = 1.f/(AS*WS);
    const float INV_P = 1.f/(PS*WS);

    // front sequence
    k_edt_row<<<(NIMG*IH+127)/128, 128>>>(pred, tru);
    k_edt_col<<<(NIMG*NPIX+255)/256, 256>>>();
    k_wsumT  <<<(DM*256+255)/256, 256>>>(patchw);
    k_gemm_w<<<dim3(DM/128, (NIMG*NPATCH)/128), 512, SMEM_GH>>>(
        p0, p1, ws0, ws1, patchb, nullptr, ptok, nullptr, nullptr,
        NIMG*NPATCH, DM, 256, INV_P, 0);
    k_assemble<<<(BT*DM+255)/256, 256>>>(cls, pos);

    // weight prep
    k_tsplit<<<dim3(2304/32, DM/32, NL),  dim3(32,8)>>>(qkvw,  q0, q1, DM,   2304);
    k_tsplit<<<dim3(DM/32,   DM/32, NL),  dim3(32,8)>>>(projw, pr0, pr1, DM, DM);
    k_tsplit<<<dim3(3072/32, DM/32, NL),  dim3(32,8)>>>(fc1w,  f10, f11, DM, 3072);
    k_tsplit<<<dim3(DM/32, 3072/32, NL),  dim3(32,8)>>>(fc2w,  f20, f21, 3072, DM);

    int MT = (BT + 127) / 128;   // 19
    int NCMB = (NIMG*NHD*NT + 255) / 256;

    // layer-0 ln1
    k_ln<<<BT, 256>>>(px, h0, h1, ln1g, ln1b);

    for (int l = 0; l < NL - 1; l++) {
        k_gemm_h<<<dim3(2304/128, MT), 256, SMEM_GH>>>(
            h0, h1, q0 + (size_t)l*2304*DM, q1 + (size_t)l*2304*DM,
            qkvb + (size_t)l*2304, nullptr, nullptr, qk0, qk1,
            BT, 2304, DM, DM, INV_W, 3);
        k_scores_h<<<dim3(5, 5, NIMG*NHD), 256, SMEM_SC>>>();
        k_combine <<<NCMB, 256>>>();
        k_av_h    <<<dim3(5, NIMG*NHD), 256, SMEM_AV>>>();
        k_gemm_h<<<dim3(DM/128, MT, 2), 256, SMEM_GH>>>(
            a0, a1, pr0 + (size_t)l*DM*DM, pr1 + (size_t)l*DM*DM,
            nullptr, nullptr, ppart, nullptr, nullptr,
            BT, DM, 384, 768, INV_W, 4);
        k_redln<<<BT, 256>>>(ppart, 2, INV_W, projb + (size_t)l*DM, px,
                             ln2g + (size_t)l*DM, ln2b + (size_t)l*DM);
        k_gemm_h<<<dim3(3072/128, MT), 256, SMEM_GH>>>(
            h0, h1, f10 + (size_t)l*3072*DM, f11 + (size_t)l*3072*DM,
            fc1b + (size_t)l*3072, nullptr, nullptr, m0, m1,
            BT, 3072, DM, DM, INV_W, 1);
        k_gemm_h<<<dim3(DM/128, MT, 4), 256, SMEM_GH>>>(
            m0, m1, f20 + (size_t)l*DM*3072, f21 + (size_t)l*DM*3072,
            nullptr, nullptr, ppart, nullptr, nullptr,
            BT, DM, 768, 3072, INV_W, 4);
        k_redln<<<BT, 256>>>(ppart, 4, INV_W, fc2b + (size_t)l*DM, px,
                             ln1g + (size_t)(l+1)*DM, ln1b + (size_t)(l+1)*DM);
    }

    // ---------- thin last layer: only cls rows needed downstream ----------
    {
        const int l = NL - 1;
        // full qkv (K/V needed at all tokens)
        k_gemm_h<<<dim3(2304/128, MT), 256, SMEM_GH>>>(
            h0, h1, q0 + (size_t)l*2304*DM, q1 + (size_t)l*2304*DM,
            qkvb + (size_t)l*2304, nullptr, nullptr, qk0, qk1,
            BT, 2304, DM, DM, INV_W, 3);
        // scores: only query m-tile 0 (contains cls row 0 of each bh)
        k_scores_h<<<dim3(5, 1, NIMG*NHD), 256, SMEM_SC>>>();
        k_combine <<<NCMB, 256>>>();
        // AV: m-tile 0 only
        k_av_h<<<dim3(1, NIMG*NHD), 256, SMEM_AV>>>();
        // gather cls rows of attention output + residual x
        k_gather4<<<4, 256>>>();
        // proj thin (M=4): out = proj(ac)*inv + bias + xc
        k_gemm_h<<<dim3(DM/128, 1), 256, SMEM_GH>>>(
            ac0, ac1, pr0 + (size_t)l*DM*DM, pr1 + (size_t)l*DM*DM,
            projb + (size_t)l*DM, pxc, pxc2, nullptr, nullptr,
            4, DM, DM, DM, INV_W, 2);
        // ln2 thin
        k_ln<<<4, 256>>>(pxc2, hc0, hc1, ln2g + (size_t)l*DM, ln2b + (size_t)l*DM);
        // fc1 thin (gelu -> split planes)
        k_gemm_h<<<dim3(3072/128, 1), 256, SMEM_GH>>>(
            hc0, hc1, f10 + (size_t)l*3072*DM, f11 + (size_t)l*3072*DM,
            fc1b + (size_t)l*3072, nullptr, nullptr, mc0, mc1,
            4, 3072, DM, DM, INV_W, 1);
        // fc2 thin (+ residual xc2)
        k_gemm_h<<<dim3(DM/128, 1), 256, SMEM_GH>>>(
            mc0, mc1, f20 + (size_t)l*DM*3072, f21 + (size_t)l*DM*3072,
            fc2b + (size_t)l*DM, pxc2, pxf, nullptr, nullptr,
            4, DM, 3072, 3072, INV_W, 2);
        // final LN on 4 compact rows
        k_lnf<<<4, 256>>>(pxf, phf, normg, normb);
    }

    k_loss<<<1, 256>>>((float*)d_out);
}